// round 12
// baseline (speedup 1.0000x reference)
#include <cuda_runtime.h>
#include <cuda_fp16.h>
#include <math.h>

#define S_    2048
#define HID_  2048
#define H_    16
#define NOPE_ 128
#define ROPE_ 64
#define VDIM_ 128
#define QR_   1536
#define KVR_  512
#define IH_   16
#define ID_   128
#define TOPK_ 512
#define EPS_  1e-6f
#define CKVX_ 640          // extended ckv row: 512 ckv | 64 kpe-src | 16 iw | 48 pad

typedef unsigned long long u64;

// ---------------- packed f32x2 helpers (bit-identical to two scalar FFMAs) ----------------
__device__ __forceinline__ void ffma2(u64 &d, u64 a, u64 b) {
    asm("fma.rn.f32x2 %0, %1, %2, %0;" : "+l"(d) : "l"(a), "l"(b));
}
__device__ __forceinline__ u64 pack2(float lo, float hi) {
    u64 r; asm("mov.b64 %0, {%1, %2};" : "=l"(r) : "f"(lo), "f"(hi)); return r;
}
__device__ __forceinline__ float2 unpack2(u64 v) {
    float2 r; asm("mov.b64 {%0, %1}, %2;" : "=f"(r.x), "=f"(r.y) : "l"(v)); return r;
}

// ---------------- scratch ----------------
__device__ float  g_qr    [S_*QR_];
__device__ float  g_q     [S_*H_*(NOPE_+ROPE_)];
__device__ float  g_ckvx  [S_*CKVX_];
__device__ float  g_bext  [CKVX_*HID_];
__device__ float  g_ckvn  [S_*KVR_];
__device__ __half g_kpeh  [S_*ROPE_];              // fp16 kpe — gather path only
__device__ __half g_kvh   [S_*H_*(NOPE_+VDIM_)];   // fp16 KV — gather path only
__device__ float  g_iq    [S_*IH_*ID_];
__device__ float  g_ikpre [S_*ID_];
__device__ float  g_ik    [S_*ID_];
__device__ float  g_scores[S_*S_];
__device__ int    g_sel   [S_*TOPK_];
__device__ int    g_nsel  [S_];
__device__ float  g_attn  [S_*H_*VDIM_];
__device__ float  g_cosb  [S_*32];
__device__ float  g_sinb  [S_*32];

// ---------------- helpers ----------------
__device__ __forceinline__ float blockReduceSum(float v, float* sh) {
    int lane = threadIdx.x & 31, w = threadIdx.x >> 5;
    #pragma unroll
    for (int o = 16; o; o >>= 1) v += __shfl_xor_sync(0xffffffffu, v, o);
    if (lane == 0) sh[w] = v;
    __syncthreads();
    int nw = (blockDim.x + 31) >> 5;
    float r = (threadIdx.x < nw) ? sh[threadIdx.x] : 0.f;
    if (w == 0) {
        #pragma unroll
        for (int o = 16; o; o >>= 1) r += __shfl_xor_sync(0xffffffffu, r, o);
        if (lane == 0) sh[0] = r;
    }
    __syncthreads();
    float out = sh[0];
    __syncthreads();
    return out;
}

// ---------------- cos/sin (bit-exact numpy float32 path) ----------------
__global__ void cossin_kernel() {
    int s = blockIdx.x, d = threadIdx.x;
    float e = (float)(2 * d) / 64.0f;
    float pf = (float)pow(10000.0, (double)e);
    float inv = __fdiv_rn(1.0f, pf);
    float f = __fmul_rn((float)s, inv);
    g_cosb[s * 32 + d] = (float)cos((double)f);
    g_sinb[s * 32 + d] = (float)sin((double)f);
}

// ---------------- build extended B slab: kv_a_w | 0.25*idx_wproj_w | zeros ----------------
__global__ __launch_bounds__(256) void build_bext_kernel(
    const float* __restrict__ kv_a_w, const float* __restrict__ idx_wproj_w)
{
    size_t idx = (size_t)blockIdx.x * 256 + threadIdx.x;
    size_t row = idx / (HID_ / 4), c4 = idx % (HID_ / 4);
    float4 v;
    if (row < 576) {
        v = reinterpret_cast<const float4*>(kv_a_w)[row * (HID_ / 4) + c4];
    } else if (row < 592) {
        v = reinterpret_cast<const float4*>(idx_wproj_w)[(row - 576) * (HID_ / 4) + c4];
        v.x *= 0.25f; v.y *= 0.25f; v.z *= 0.25f; v.w *= 0.25f;
    } else {
        v = make_float4(0.f, 0.f, 0.f, 0.f);
    }
    reinterpret_cast<float4*>(g_bext)[idx] = v;
}

// ============ shared GEMM body: 128x128 tile, quadrant microtile, FFMA2 ============
template<bool HALF_OUT>
__device__ __forceinline__ void gemm_body_128(
    const float* __restrict__ A, int lda,
    const float* __restrict__ B, int ldb,
    float* __restrict__ C, int ldc,
    int M, int N, int K, float alpha,
    int m0, int n0,
    float (*As)[8][128], float (*Bs)[8][128])
{
    int t = threadIdx.x;
    int tx = t & 15, ty = t >> 4;
    int a_m = t >> 1, a_k = (t & 1) * 4;
    int gmA = m0 + a_m, gnB = n0 + a_m;
    u64 acc[8][4];
    #pragma unroll
    for (int i = 0; i < 8; i++)
        #pragma unroll
        for (int j = 0; j < 4; j++) acc[i][j] = 0ull;

    float4 va = make_float4(0.f,0.f,0.f,0.f), vb = va;
    if (gmA < M) va = *reinterpret_cast<const float4*>(&A[(size_t)gmA * lda + a_k]);
    if (gnB < N) vb = *reinterpret_cast<const float4*>(&B[(size_t)gnB * ldb + a_k]);
    As[0][a_k+0][a_m]=va.x; As[0][a_k+1][a_m]=va.y; As[0][a_k+2][a_m]=va.z; As[0][a_k+3][a_m]=va.w;
    Bs[0][a_k+0][a_m]=vb.x; Bs[0][a_k+1][a_m]=vb.y; Bs[0][a_k+2][a_m]=vb.z; Bs[0][a_k+3][a_m]=vb.w;
    __syncthreads();
    int buf = 0;
    for (int k0 = 0; k0 < K; k0 += 8) {
        bool nxt = (k0 + 8) < K;
        if (nxt) {
            va = make_float4(0.f,0.f,0.f,0.f); vb = va;
            if (gmA < M) va = *reinterpret_cast<const float4*>(&A[(size_t)gmA * lda + k0 + 8 + a_k]);
            if (gnB < N) vb = *reinterpret_cast<const float4*>(&B[(size_t)gnB * ldb + k0 + 8 + a_k]);
        }
        #pragma unroll
        for (int k = 0; k < 8; k++) {
            float4 a0 = *reinterpret_cast<const float4*>(&As[buf][k][ty * 4]);
            float4 a1 = *reinterpret_cast<const float4*>(&As[buf][k][64 + ty * 4]);
            float4 b0 = *reinterpret_cast<const float4*>(&Bs[buf][k][tx * 4]);
            float4 b1 = *reinterpret_cast<const float4*>(&Bs[buf][k][64 + tx * 4]);
            u64 bb[4] = {pack2(b0.x,b0.y), pack2(b0.z,b0.w), pack2(b1.x,b1.y), pack2(b1.z,b1.w)};
            float ra[8] = {a0.x,a0.y,a0.z,a0.w,a1.x,a1.y,a1.z,a1.w};
            #pragma unroll
            for (int i = 0; i < 8; i++) {
                u64 aa = pack2(ra[i], ra[i]);
                #pragma unroll
                for (int j = 0; j < 4; j++) ffma2(acc[i][j], aa, bb[j]);
            }
        }
        if (nxt) {
            int nb = buf ^ 1;
            As[nb][a_k+0][a_m]=va.x; As[nb][a_k+1][a_m]=va.y; As[nb][a_k+2][a_m]=va.z; As[nb][a_k+3][a_m]=va.w;
            Bs[nb][a_k+0][a_m]=vb.x; Bs[nb][a_k+1][a_m]=vb.y; Bs[nb][a_k+2][a_m]=vb.z; Bs[nb][a_k+3][a_m]=vb.w;
            __syncthreads();
            buf = nb;
        }
    }
    #pragma unroll
    for (int i = 0; i < 8; i++) {
        int gm = m0 + ((i < 4) ? (ty * 4 + i) : (64 + ty * 4 + i - 4));
        if (gm >= M) continue;
        #pragma unroll
        for (int j = 0; j < 4; j++) {
            float2 v = unpack2(acc[i][j]);
            int gn = n0 + ((j < 2) ? (tx * 4 + j * 2) : (64 + tx * 4 + (j - 2) * 2));
            if (HALF_OUT) {
                __half2 hv = __floats2half2_rn(v.x, v.y);
                *reinterpret_cast<__half2*>(reinterpret_cast<__half*>(C) + (size_t)gm * ldc + gn) = hv;
            } else {
                if (gn < N)     C[(size_t)gm * ldc + gn]     = alpha * v.x;
                if (gn + 1 < N) C[(size_t)gm * ldc + gn + 1] = alpha * v.y;
            }
        }
    }
}

// ---------------- generic 128x128 GEMM (o_w) ----------------
__global__ __launch_bounds__(256, 2) void sgemm_nt_db(
    const float* __restrict__ A, int lda,
    const float* __restrict__ B, int ldb,
    float* __restrict__ C, int ldc,
    int M, int N, int K, float alpha)
{
    __shared__ float As[2][8][128];
    __shared__ float Bs[2][8][128];
    gemm_body_128<false>(A, lda, B, ldb, C, ldc, M, N, K, alpha,
                         blockIdx.y * 128, blockIdx.x * 128, As, Bs);
}

// ---------------- fused A=hidden (K=2048): qr | ckvx(incl iw) | ik — 288 blocks ----------------
__global__ __launch_bounds__(256, 2) void fused_hidden_gemm(
    const float* __restrict__ A,
    const float* __restrict__ Bqr, const float* __restrict__ Bik)
{
    __shared__ float As[2][8][128];
    __shared__ float Bs[2][8][128];
    int bx = blockIdx.x;
    const float* B; float* C; int N, ldc, n0;
    if (bx < 12)      { B = Bqr;    C = g_qr;    N = QR_;   ldc = QR_;   n0 = bx * 128; }
    else if (bx < 17) { B = g_bext; C = g_ckvx;  N = CKVX_; ldc = CKVX_; n0 = (bx - 12) * 128; }
    else              { B = Bik;    C = g_ikpre; N = ID_;   ldc = ID_;   n0 = 0; }
    gemm_body_128<false>(A, HID_, B, HID_, C, ldc, S_, N, HID_, 1.f,
                         blockIdx.y * 128, n0, As, Bs);
}

// ---------------- fused q | iq | kv_b(fp16 out): backfilled tail ----------------
__global__ __launch_bounds__(256, 2) void fused_qr_kv_gemm(
    const float* __restrict__ Bq, const float* __restrict__ Biq,
    const float* __restrict__ Bkv)
{
    __shared__ float As[2][8][128];
    __shared__ float Bs[2][8][128];
    int bx = blockIdx.x;
    if (bx < 40) {
        const float* B; float* C; int N, n0;
        if (bx < 24) { B = Bq;  C = g_q;  N = H_ * 192;  n0 = bx * 128; }
        else         { B = Biq; C = g_iq; N = IH_ * ID_; n0 = (bx - 24) * 128; }
        gemm_body_128<false>(g_qr, QR_, B, QR_, C, N, S_, N, QR_, 1.f,
                             blockIdx.y * 128, n0, As, Bs);
    } else {
        gemm_body_128<true>(g_ckvn, KVR_, Bkv, KVR_,
                            reinterpret_cast<float*>(g_kvh), H_ * 256,
                            S_, H_ * 256, KVR_, 1.f,
                            blockIdx.y * 128, (bx - 40) * 128, As, Bs);
    }
}

// ---------------- rmsnorm (in-place) ----------------
__global__ __launch_bounds__(256) void rmsnorm_kernel(float* __restrict__ x,
                                                      const float* __restrict__ w, int n) {
    __shared__ float sh[33];
    int row = blockIdx.x, t = threadIdx.x;
    float* p = x + (size_t)row * n;
    int cnt = n / 256;
    float local[8];
    float ss = 0.f;
    for (int i = 0; i < cnt; i++) { float v = p[t + i * 256]; local[i] = v; ss += v * v; }
    float total = blockReduceSum(ss, sh);
    float scale = rsqrtf(total / (float)n + EPS_);
    for (int i = 0; i < cnt; i++) p[t + i * 256] = local[i] * scale * w[t + i * 256];
}

// ---------------- ckv split (reads extended row; kpe stored fp16) ----------------
__global__ __launch_bounds__(256) void ckv_split_kernel(const float* __restrict__ w) {
    __shared__ float sh[33];
    int s = blockIdx.x, t = threadIdx.x;
    const float* p = g_ckvx + (size_t)s * CKVX_;
    float v0 = p[t], v1 = p[256 + t];
    float total = blockReduceSum(v0 * v0 + v1 * v1, sh);
    float scale = rsqrtf(total / (float)KVR_ + EPS_);
    g_ckvn[(size_t)s * KVR_ + t] = v0 * scale * w[t];
    g_ckvn[(size_t)s * KVR_ + 256 + t] = v1 * scale * w[256 + t];
    if (t < 32) {
        float x1 = p[KVR_ + t], x2 = p[KVR_ + 32 + t];
        float c = g_cosb[s * 32 + t], sn = g_sinb[s * 32 + t];
        g_kpeh[s * ROPE_ + t]      = __float2half_rn(x1 * c - x2 * sn);
        g_kpeh[s * ROPE_ + 32 + t] = __float2half_rn(x2 * c + x1 * sn);
    }
}

// ---------------- layernorm + rope for ik ----------------
__global__ __launch_bounds__(128) void ik_ln_rope_kernel(const float* __restrict__ xin,
                                                         const float* __restrict__ w,
                                                         const float* __restrict__ b) {
    __shared__ float sh[33];
    __shared__ float sn_[128];
    int s = blockIdx.x, t = threadIdx.x;
    float x = xin[(size_t)s * ID_ + t];
    float mean = blockReduceSum(x, sh) / (float)ID_;
    float var = blockReduceSum(x * x, sh) / (float)ID_ - mean * mean;
    float nv = (x - mean) * rsqrtf(var + EPS_) * w[t] + b[t];
    sn_[t] = nv;
    __syncthreads();
    float out;
    if (t < 32) {
        float c = g_cosb[s * 32 + t], snv = g_sinb[s * 32 + t];
        out = sn_[t] * c - sn_[t + 32] * snv;
    } else if (t < 64) {
        float c = g_cosb[s * 32 + (t - 32)], snv = g_sinb[s * 32 + (t - 32)];
        out = sn_[t] * c + sn_[t - 32] * snv;
    } else {
        out = nv;
    }
    g_ik[(size_t)s * ID_ + t] = out;
}

// ---------------- generic in-place rope over heads ----------------
__global__ void rope_kernel(float* __restrict__ base, int rowStride, int headStride) {
    int s = blockIdx.x;
    int h = threadIdx.y, d = threadIdx.x;
    float* p = base + (size_t)s * rowStride + h * headStride;
    float c = g_cosb[s * 32 + d], sn = g_sinb[s * 32 + d];
    float x1 = p[d], x2 = p[d + 32];
    p[d] = x1 * c - x2 * sn;
    p[d + 32] = x2 * c + x1 * sn;
}

// ============ fused indexer w/ FFMA2 + causal skip (iw from g_ckvx col 576+h) ============
__global__ __launch_bounds__(256, 2) void idx_scores_kernel() {
    int m0 = blockIdx.y * 128, n0 = blockIdx.x * 64;
    int t = threadIdx.x;
    int tx = t & 15, ty = t >> 4;
    const float NINF = __int_as_float(0xff800000);

    if (m0 + 128 <= TOPK_) return;
    if (n0 >= m0 + 128) {
        #pragma unroll
        for (int i = 0; i < 8; i++) {
            int gm = m0 + ty * 8 + i;
            #pragma unroll
            for (int j = 0; j < 4; j++)
                g_scores[(size_t)gm * S_ + n0 + tx * 4 + j] = NINF;
        }
        return;
    }

    __shared__ float Bs[128][64];
    __shared__ float As[2][8][128];
    int a_m = t >> 1, a_k = (t & 1) * 4;

    for (int i = t; i < 64 * 32; i += 256) {
        int nl = i >> 5, k4 = (i & 31) * 4;
        float4 v = *reinterpret_cast<const float4*>(&g_ik[(size_t)(n0 + nl) * ID_ + k4]);
        Bs[k4+0][nl] = v.x; Bs[k4+1][nl] = v.y; Bs[k4+2][nl] = v.z; Bs[k4+3][nl] = v.w;
    }

    float sacc[8][4];
    #pragma unroll
    for (int i = 0; i < 8; i++)
        #pragma unroll
        for (int j = 0; j < 4; j++) sacc[i][j] = 0.f;
    __syncthreads();

    const size_t lda = IH_ * ID_;
    for (int h = 0; h < IH_; h++) {
        const float* A = g_iq + (size_t)h * ID_ + (size_t)(m0 + a_m) * lda;
        {
            float4 v = *reinterpret_cast<const float4*>(&A[a_k]);
            As[0][a_k+0][a_m]=v.x; As[0][a_k+1][a_m]=v.y; As[0][a_k+2][a_m]=v.z; As[0][a_k+3][a_m]=v.w;
        }
        __syncthreads();
        u64 tacc[8][2];
        #pragma unroll
        for (int i = 0; i < 8; i++) { tacc[i][0] = 0ull; tacc[i][1] = 0ull; }
        int buf = 0;
        for (int k0 = 0; k0 < 128; k0 += 8) {
            float4 v;
            bool nxt = (k0 + 8) < 128;
            if (nxt) v = *reinterpret_cast<const float4*>(&A[k0 + 8 + a_k]);
            #pragma unroll
            for (int k = 0; k < 8; k++) {
                float4 a0 = *reinterpret_cast<const float4*>(&As[buf][k][ty * 8]);
                float4 a1 = *reinterpret_cast<const float4*>(&As[buf][k][ty * 8 + 4]);
                float4 b0 = *reinterpret_cast<const float4*>(&Bs[k0 + k][tx * 4]);
                u64 bb[2] = {pack2(b0.x,b0.y), pack2(b0.z,b0.w)};
                float ra[8] = {a0.x,a0.y,a0.z,a0.w,a1.x,a1.y,a1.z,a1.w};
                #pragma unroll
                for (int i = 0; i < 8; i++) {
                    u64 aa = pack2(ra[i], ra[i]);
                    ffma2(tacc[i][0], aa, bb[0]);
                    ffma2(tacc[i][1], aa, bb[1]);
                }
            }
            if (nxt) {
                int nb = buf ^ 1;
                As[nb][a_k+0][a_m]=v.x; As[nb][a_k+1][a_m]=v.y; As[nb][a_k+2][a_m]=v.z; As[nb][a_k+3][a_m]=v.w;
                __syncthreads();
                buf = nb;
            }
        }
        __syncthreads();
        #pragma unroll
        for (int i = 0; i < 8; i++) {
            float w = g_ckvx[(size_t)(m0 + ty * 8 + i) * CKVX_ + 576 + h];
            float2 t01 = unpack2(tacc[i][0]);
            float2 t23 = unpack2(tacc[i][1]);
            float tv[4] = {t01.x, t01.y, t23.x, t23.y};
            #pragma unroll
            for (int j = 0; j < 4; j++) {
                float add = __fmul_rn(w, fmaxf(tv[j], 0.f));
                sacc[i][j] = __fadd_rn(sacc[i][j], add);
            }
        }
    }
    #pragma unroll
    for (int i = 0; i < 8; i++) {
        int gm = m0 + ty * 8 + i;
        #pragma unroll
        for (int j = 0; j < 4; j++) {
            int gn = n0 + tx * 4 + j;
            g_scores[(size_t)gm * S_ + gn] = (gn <= gm) ? sacc[i][j] : NINF;
        }
    }
}

// ---------------- top-k (stable, jax tie semantics) ----------------
__device__ __forceinline__ unsigned fkey(float f) {
    unsigned u = __float_as_uint(f);
    return u ^ ((u >> 31) ? 0xFFFFFFFFu : 0x80000000u);
}

__global__ __launch_bounds__(256) void topk_kernel() {
    int q = blockIdx.x, t = threadIdx.x;
    const float* sc = g_scores + (size_t)q * S_;
    if (q < TOPK_) {
        for (int i = t; i <= q; i += 256) g_sel[(size_t)q * TOPK_ + i] = i;
        if (t == 0) g_nsel[q] = q + 1;
        return;
    }
    __shared__ unsigned hist[256];
    __shared__ unsigned s_pref, s_r;
    __shared__ int s_gt[257], s_eq[257];

    unsigned pref = 0, r = TOPK_;
    #pragma unroll
    for (int p = 3; p >= 0; p--) {
        hist[t] = 0;
        __syncthreads();
        for (int i = t; i < S_; i += 256) {
            unsigned u = fkey(sc[i]);
            bool ok = (p == 3) || ((u >> ((p + 1) * 8)) == pref);
            if (ok) atomicAdd(&hist[(u >> (p * 8)) & 255], 1u);
        }
        __syncthreads();
        if (t == 0) {
            unsigned run = 0;
            int b = 255;
            for (; b >= 0; b--) {
                unsigned c = hist[b];
                if (run + c >= r) break;
                run += c;
            }
            s_pref = (pref << 8) | (unsigned)b;
            s_r = r - run;
        }
        __syncthreads();
        pref = s_pref; r = s_r;
        __syncthreads();
    }
    unsigned T = pref;
    int need_eq = (int)r;

    int i0 = t * 8;
    unsigned keys[8];
    int cg = 0, ce = 0;
    #pragma unroll
    for (int k = 0; k < 8; k++) {
        unsigned u = fkey(sc[i0 + k]);
        keys[k] = u;
        cg += (u > T);
        ce += (u == T);
    }
    s_gt[t] = cg; s_eq[t] = ce;
    __syncthreads();
    if (t == 0) {
        int rg = 0, re = 0;
        for (int i = 0; i < 256; i++) {
            int a = s_gt[i]; s_gt[i] = rg; rg += a;
            int b2 = s_eq[i]; s_eq[i] = re; re += b2;
        }
        s_gt[256] = rg;
    }
    __syncthreads();
    int gpos = s_gt[t], epos = s_eq[t], total_gt = s_gt[256];
    int* out = g_sel + (size_t)q * TOPK_;
    #pragma unroll
    for (int k = 0; k < 8; k++) {
        unsigned u = keys[k];
        if (u > T) out[gpos++] = i0 + k;
        else if (u == T) {
            if (epos < need_eq) out[total_gt + epos] = i0 + k;
            epos++;
        }
    }
    if (t == 0) g_nsel[q] = TOPK_;
}

// ============ sparse attention: 4 heads per block (4 validated 4-warp groups) ============
// Per-head structure/order identical to the round-10 kernel; kpe fp16; the 4 head-groups
// share kpe cache lines in L1, cutting kpe L2 traffic 4x.
__global__ __launch_bounds__(512) void sparse_attn_kernel() {
    const float SCALE = 0.07216878364870322f;
    int qi = blockIdx.x;
    int t = threadIdx.x;
    int hw = t >> 7;                 // head group 0..3 (warps 4hw..4hw+3)
    int tg = t & 127;                // thread within head group
    int w = tg >> 5, lane = t & 31;  // warp-in-group, lane
    int h = blockIdx.y * 4 + hw;

    __shared__ float qv[4][192];
    __shared__ float s_p[4][TOPK_];
    __shared__ int   s_idx[TOPK_];
    __shared__ float s_red[4][4];
    __shared__ float s_out[4][4][128];

    int n = g_nsel[qi];
    const float* qptr = g_q + (size_t)qi * (H_ * 192) + h * 192;
    for (int i = tg; i < 192; i += 128) qv[hw][i] = qptr[i];
    for (int i = t; i < n; i += 512) s_idx[i] = g_sel[(size_t)qi * TOPK_ + i];
    __syncthreads();

    for (int j = w; j < n; j += 4) {
        int kidx = s_idx[j];
        const __half* kh = g_kvh + (size_t)kidx * (H_ * 256) + h * 256;
        uint2 raw = *reinterpret_cast<const uint2*>(kh + lane * 4);
        float2 f01 = __half22float2(*reinterpret_cast<const __half2*>(&raw.x));
        float2 f23 = __half22float2(*reinterpret_cast<const __half2*>(&raw.y));
        float4 a = reinterpret_cast<const float4*>(qv[hw])[lane];
        float d = a.x * f01.x + a.y * f01.y + a.z * f23.x + a.w * f23.y;
        unsigned rawp = *reinterpret_cast<const unsigned*>(g_kpeh + (size_t)kidx * ROPE_ + lane * 2);
        float2 bp = __half22float2(*reinterpret_cast<const __half2*>(&rawp));
        float2 ap = reinterpret_cast<const float2*>(qv[hw] + 128)[lane];
        d += ap.x * bp.x + ap.y * bp.y;
        #pragma unroll
        for (int o = 16; o; o >>= 1) d += __shfl_down_sync(0xffffffffu, d, o);
        if (lane == 0) s_p[hw][j] = d * SCALE;
    }
    __syncthreads();

    float m = -3.4e38f;
    for (int i = tg; i < n; i += 128) m = fmaxf(m, s_p[hw][i]);
    #pragma unroll
    for (int o = 16; o; o >>= 1) m = fmaxf(m, __shfl_xor_sync(0xffffffffu, m, o));
    if (lane == 0) s_red[hw][w] = m;
    __syncthreads();
    m = fmaxf(fmaxf(s_red[hw][0], s_red[hw][1]), fmaxf(s_red[hw][2], s_red[hw][3]));
    __syncthreads();

    float sum = 0.f;
    for (int i = tg; i < n; i += 128) {
        float e = __expf(s_p[hw][i] - m);
        s_p[hw][i] = e;
        sum += e;
    }
    #pragma unroll
    for (int o = 16; o; o >>= 1) sum += __shfl_xor_sync(0xffffffffu, sum, o);
    __syncthreads();
    if (lane == 0) s_red[hw][w] = sum;
    __syncthreads();
    sum = s_red[hw][0] + s_red[hw][1] + s_red[hw][2] + s_red[hw][3];
    float inv = 1.0f / sum;

    float4 acc = make_float4(0.f, 0.f, 0.f, 0.f);
    for (int j = w; j < n; j += 4) {
        float p = s_p[hw][j];
        int kidx = s_idx[j];
        const __half* vh = g_kvh + (size_t)kidx * (H_ * 256) + h * 256 + 128;
        uint2 raw = *reinterpret_cast<const uint2*>(vh + lane * 4);
        float2 v01 = __half22float2(*reinterpret_cast<const __half2*>(&raw.x));
        float2 v23 = __half22float2(*reinterpret_cast<const __half2*>(&raw.y));
        acc.x += p * v01.x; acc.y += p * v01.y; acc.z += p * v23.x; acc.w += p * v23.y;
    }
    reinterpret_cast<float4*>(&s_out[hw][w][0])[lane] = acc;
    __syncthreads();
    float o = (s_out[hw][0][tg] + s_out[hw][1][tg] + s_out[hw][2][tg] + s_out[hw][3][tg]) * inv;
    g_attn[(size_t)qi * (H_ * VDIM_) + h * VDIM_ + tg] = o;
}

// ---------------- launch ----------------
extern "C" void kernel_launch(void* const* d_in, const int* in_sizes, int n_in,
                              void* d_out, int out_size) {
    (void)in_sizes; (void)n_in; (void)out_size;
    const float* hidden      = (const float*)d_in[0];
    const float* q_a_w       = (const float*)d_in[1];
    const float* q_a_ln_w    = (const float*)d_in[2];
    const float* q_b_w       = (const float*)d_in[3];
    const float* kv_a_w      = (const float*)d_in[4];
    const float* kv_a_ln_w   = (const float*)d_in[5];
    const float* kv_b_w      = (const float*)d_in[6];
    const float* o_w         = (const float*)d_in[7];
    const float* idx_wq_b_w  = (const float*)d_in[8];
    const float* idx_wk_w    = (const float*)d_in[9];
    const float* idx_kn_w    = (const float*)d_in[10];
    const float* idx_kn_b    = (const float*)d_in[11];
    const float* idx_wproj_w = (const float*)d_in[12];
    float* out = (float*)d_out;

    float *p_qr, *p_q, *p_iq, *p_ikpre, *p_attn;
    cudaGetSymbolAddress((void**)&p_qr,    g_qr);
    cudaGetSymbolAddress((void**)&p_q,     g_q);
    cudaGetSymbolAddress((void**)&p_iq,    g_iq);
    cudaGetSymbolAddress((void**)&p_ikpre, g_ikpre);
    cudaGetSymbolAddress((void**)&p_attn,  g_attn);

    dim3 tb(256);

    cossin_kernel<<<S_, 32>>>();
    build_bext_kernel<<<(CKVX_ * HID_ / 4 + 255) / 256, 256>>>(kv_a_w, idx_wproj_w);

    // qr | ckvx(incl 0.25*iw) | ik — 288 blocks, single wave over A=hidden (K=2048)
    fused_hidden_gemm<<<dim3(18, S_ / 128), tb>>>(hidden, q_a_w, idx_wk_w);
    rmsnorm_kernel<<<S_, 256>>>(p_qr, q_a_ln_w, QR_);
    ckv_split_kernel<<<S_, 256>>>(kv_a_ln_w);
    ik_ln_rope_kernel<<<S_, 128>>>(p_ikpre, idx_kn_w, idx_kn_b);

    // q | iq (K=1536) with kv_b (K=512, fp16 out) backfilling the tail wave
    fused_qr_kv_gemm<<<dim3(72, S_ / 128), tb>>>(q_b_w, idx_wq_b_w, kv_b_w);

    // rope q_pe and iq
    rope_kernel<<<S_, dim3(32, H_)>>>(p_q + NOPE_, H_ * 192, 192);
    rope_kernel<<<S_, dim3(32, IH_)>>>(p_iq, IH_ * ID_, ID_);

    // fused indexer scores (causal skip + FFMA2)
    idx_scores_kernel<<<dim3(S_ / 64, S_ / 128), tb>>>();

    topk_kernel<<<S_, 256>>>();

    sparse_attn_kernel<<<dim3(S_, H_ / 4), 512>>>();

    // out = attn @ o_w^T   [S, 2048]
    sgemm_nt_db<<<dim3(HID_ / 128, S_ / 128), tb>>>(p_attn, H_ * VDIM_, o_w, H_ * VDIM_, out, HID_, S_, HID_, H_ * VDIM_, 1.f);
}

// round 13
// speedup vs baseline: 1.0368x; 1.0368x over previous
#include <cuda_runtime.h>
#include <cuda_fp16.h>
#include <math.h>

#define S_    2048
#define HID_  2048
#define H_    16
#define NOPE_ 128
#define ROPE_ 64
#define VDIM_ 128
#define QR_   1536
#define KVR_  512
#define IH_   16
#define ID_   128
#define TOPK_ 512
#define EPS_  1e-6f
#define CKVX_ 640          // extended ckv row: 512 ckv | 64 kpe-src | 16 iw | 48 pad

typedef unsigned long long u64;

// ---------------- packed f32x2 helpers (bit-identical to two scalar FFMAs) ----------------
__device__ __forceinline__ void ffma2(u64 &d, u64 a, u64 b) {
    asm("fma.rn.f32x2 %0, %1, %2, %0;" : "+l"(d) : "l"(a), "l"(b));
}
__device__ __forceinline__ u64 pack2(float lo, float hi) {
    u64 r; asm("mov.b64 %0, {%1, %2};" : "=l"(r) : "f"(lo), "f"(hi)); return r;
}
__device__ __forceinline__ float2 unpack2(u64 v) {
    float2 r; asm("mov.b64 {%0, %1}, %2;" : "=f"(r.x), "=f"(r.y) : "l"(v)); return r;
}

// ---------------- scratch ----------------
__device__ float  g_qr    [S_*QR_];
__device__ float  g_q     [S_*H_*(NOPE_+ROPE_)];
__device__ float  g_ckvx  [S_*CKVX_];
__device__ float  g_bext  [CKVX_*HID_];
__device__ float  g_ckvn  [S_*KVR_];
__device__ __half g_kpeh  [S_*ROPE_];              // fp16 kpe — gather path only
__device__ __half g_kvh   [S_*H_*(NOPE_+VDIM_)];   // fp16 KV — gather path only
__device__ float  g_iq    [S_*IH_*ID_];
__device__ float  g_ikpre [S_*ID_];
__device__ float  g_ik    [S_*ID_];
__device__ float  g_scores[S_*S_];
__device__ int    g_sel   [S_*TOPK_];
__device__ int    g_nsel  [S_];
__device__ float  g_attn  [S_*H_*VDIM_];
__device__ float  g_cosb  [S_*32];
__device__ float  g_sinb  [S_*32];

// ---------------- helpers ----------------
__device__ __forceinline__ float blockReduceSum(float v, float* sh) {
    int lane = threadIdx.x & 31, w = threadIdx.x >> 5;
    #pragma unroll
    for (int o = 16; o; o >>= 1) v += __shfl_xor_sync(0xffffffffu, v, o);
    if (lane == 0) sh[w] = v;
    __syncthreads();
    int nw = (blockDim.x + 31) >> 5;
    float r = (threadIdx.x < nw) ? sh[threadIdx.x] : 0.f;
    if (w == 0) {
        #pragma unroll
        for (int o = 16; o; o >>= 1) r += __shfl_xor_sync(0xffffffffu, r, o);
        if (lane == 0) sh[0] = r;
    }
    __syncthreads();
    float out = sh[0];
    __syncthreads();
    return out;
}

// ---------------- cos/sin (bit-exact numpy float32 path) ----------------
__global__ void cossin_kernel() {
    int s = blockIdx.x, d = threadIdx.x;
    float e = (float)(2 * d) / 64.0f;
    float pf = (float)pow(10000.0, (double)e);
    float inv = __fdiv_rn(1.0f, pf);
    float f = __fmul_rn((float)s, inv);
    g_cosb[s * 32 + d] = (float)cos((double)f);
    g_sinb[s * 32 + d] = (float)sin((double)f);
}

// ---------------- build extended B slab: kv_a_w | 0.25*idx_wproj_w | zeros ----------------
__global__ __launch_bounds__(256) void build_bext_kernel(
    const float* __restrict__ kv_a_w, const float* __restrict__ idx_wproj_w)
{
    size_t idx = (size_t)blockIdx.x * 256 + threadIdx.x;
    size_t row = idx / (HID_ / 4), c4 = idx % (HID_ / 4);
    float4 v;
    if (row < 576) {
        v = reinterpret_cast<const float4*>(kv_a_w)[row * (HID_ / 4) + c4];
    } else if (row < 592) {
        v = reinterpret_cast<const float4*>(idx_wproj_w)[(row - 576) * (HID_ / 4) + c4];
        v.x *= 0.25f; v.y *= 0.25f; v.z *= 0.25f; v.w *= 0.25f;
    } else {
        v = make_float4(0.f, 0.f, 0.f, 0.f);
    }
    reinterpret_cast<float4*>(g_bext)[idx] = v;
}

// ============ shared GEMM body: 128x128 tile, quadrant microtile, FFMA2 ============
template<bool HALF_OUT>
__device__ __forceinline__ void gemm_body_128(
    const float* __restrict__ A, int lda,
    const float* __restrict__ B, int ldb,
    float* __restrict__ C, int ldc,
    int M, int N, int K, float alpha,
    int m0, int n0,
    float (*As)[8][128], float (*Bs)[8][128])
{
    int t = threadIdx.x;
    int tx = t & 15, ty = t >> 4;
    int a_m = t >> 1, a_k = (t & 1) * 4;
    int gmA = m0 + a_m, gnB = n0 + a_m;
    u64 acc[8][4];
    #pragma unroll
    for (int i = 0; i < 8; i++)
        #pragma unroll
        for (int j = 0; j < 4; j++) acc[i][j] = 0ull;

    float4 va = make_float4(0.f,0.f,0.f,0.f), vb = va;
    if (gmA < M) va = *reinterpret_cast<const float4*>(&A[(size_t)gmA * lda + a_k]);
    if (gnB < N) vb = *reinterpret_cast<const float4*>(&B[(size_t)gnB * ldb + a_k]);
    As[0][a_k+0][a_m]=va.x; As[0][a_k+1][a_m]=va.y; As[0][a_k+2][a_m]=va.z; As[0][a_k+3][a_m]=va.w;
    Bs[0][a_k+0][a_m]=vb.x; Bs[0][a_k+1][a_m]=vb.y; Bs[0][a_k+2][a_m]=vb.z; Bs[0][a_k+3][a_m]=vb.w;
    __syncthreads();
    int buf = 0;
    for (int k0 = 0; k0 < K; k0 += 8) {
        bool nxt = (k0 + 8) < K;
        if (nxt) {
            va = make_float4(0.f,0.f,0.f,0.f); vb = va;
            if (gmA < M) va = *reinterpret_cast<const float4*>(&A[(size_t)gmA * lda + k0 + 8 + a_k]);
            if (gnB < N) vb = *reinterpret_cast<const float4*>(&B[(size_t)gnB * ldb + k0 + 8 + a_k]);
        }
        #pragma unroll
        for (int k = 0; k < 8; k++) {
            float4 a0 = *reinterpret_cast<const float4*>(&As[buf][k][ty * 4]);
            float4 a1 = *reinterpret_cast<const float4*>(&As[buf][k][64 + ty * 4]);
            float4 b0 = *reinterpret_cast<const float4*>(&Bs[buf][k][tx * 4]);
            float4 b1 = *reinterpret_cast<const float4*>(&Bs[buf][k][64 + tx * 4]);
            u64 bb[4] = {pack2(b0.x,b0.y), pack2(b0.z,b0.w), pack2(b1.x,b1.y), pack2(b1.z,b1.w)};
            float ra[8] = {a0.x,a0.y,a0.z,a0.w,a1.x,a1.y,a1.z,a1.w};
            #pragma unroll
            for (int i = 0; i < 8; i++) {
                u64 aa = pack2(ra[i], ra[i]);
                #pragma unroll
                for (int j = 0; j < 4; j++) ffma2(acc[i][j], aa, bb[j]);
            }
        }
        if (nxt) {
            int nb = buf ^ 1;
            As[nb][a_k+0][a_m]=va.x; As[nb][a_k+1][a_m]=va.y; As[nb][a_k+2][a_m]=va.z; As[nb][a_k+3][a_m]=va.w;
            Bs[nb][a_k+0][a_m]=vb.x; Bs[nb][a_k+1][a_m]=vb.y; Bs[nb][a_k+2][a_m]=vb.z; Bs[nb][a_k+3][a_m]=vb.w;
            __syncthreads();
            buf = nb;
        }
    }
    #pragma unroll
    for (int i = 0; i < 8; i++) {
        int gm = m0 + ((i < 4) ? (ty * 4 + i) : (64 + ty * 4 + i - 4));
        if (gm >= M) continue;
        #pragma unroll
        for (int j = 0; j < 4; j++) {
            float2 v = unpack2(acc[i][j]);
            int gn = n0 + ((j < 2) ? (tx * 4 + j * 2) : (64 + tx * 4 + (j - 2) * 2));
            if (HALF_OUT) {
                __half2 hv = __floats2half2_rn(v.x, v.y);
                *reinterpret_cast<__half2*>(reinterpret_cast<__half*>(C) + (size_t)gm * ldc + gn) = hv;
            } else {
                if (gn < N)     C[(size_t)gm * ldc + gn]     = alpha * v.x;
                if (gn + 1 < N) C[(size_t)gm * ldc + gn + 1] = alpha * v.y;
            }
        }
    }
}

// ---------------- generic 128x128 GEMM (o_w) ----------------
__global__ __launch_bounds__(256, 2) void sgemm_nt_db(
    const float* __restrict__ A, int lda,
    const float* __restrict__ B, int ldb,
    float* __restrict__ C, int ldc,
    int M, int N, int K, float alpha)
{
    __shared__ float As[2][8][128];
    __shared__ float Bs[2][8][128];
    gemm_body_128<false>(A, lda, B, ldb, C, ldc, M, N, K, alpha,
                         blockIdx.y * 128, blockIdx.x * 128, As, Bs);
}

// ---------------- fused A=hidden (K=2048): qr | ckvx(incl iw) | ik — 288 blocks ----------------
__global__ __launch_bounds__(256, 2) void fused_hidden_gemm(
    const float* __restrict__ A,
    const float* __restrict__ Bqr, const float* __restrict__ Bik)
{
    __shared__ float As[2][8][128];
    __shared__ float Bs[2][8][128];
    int bx = blockIdx.x;
    const float* B; float* C; int N, ldc, n0;
    if (bx < 12)      { B = Bqr;    C = g_qr;    N = QR_;   ldc = QR_;   n0 = bx * 128; }
    else if (bx < 17) { B = g_bext; C = g_ckvx;  N = CKVX_; ldc = CKVX_; n0 = (bx - 12) * 128; }
    else              { B = Bik;    C = g_ikpre; N = ID_;   ldc = ID_;   n0 = 0; }
    gemm_body_128<false>(A, HID_, B, HID_, C, ldc, S_, N, HID_, 1.f,
                         blockIdx.y * 128, n0, As, Bs);
}

// ---------------- fused q | iq | kv_b(fp16 out): backfilled tail ----------------
__global__ __launch_bounds__(256, 2) void fused_qr_kv_gemm(
    const float* __restrict__ Bq, const float* __restrict__ Biq,
    const float* __restrict__ Bkv)
{
    __shared__ float As[2][8][128];
    __shared__ float Bs[2][8][128];
    int bx = blockIdx.x;
    if (bx < 40) {
        const float* B; float* C; int N, n0;
        if (bx < 24) { B = Bq;  C = g_q;  N = H_ * 192;  n0 = bx * 128; }
        else         { B = Biq; C = g_iq; N = IH_ * ID_; n0 = (bx - 24) * 128; }
        gemm_body_128<false>(g_qr, QR_, B, QR_, C, N, S_, N, QR_, 1.f,
                             blockIdx.y * 128, n0, As, Bs);
    } else {
        gemm_body_128<true>(g_ckvn, KVR_, Bkv, KVR_,
                            reinterpret_cast<float*>(g_kvh), H_ * 256,
                            S_, H_ * 256, KVR_, 1.f,
                            blockIdx.y * 128, (bx - 40) * 128, As, Bs);
    }
}

// ---------------- rmsnorm (in-place) ----------------
__global__ __launch_bounds__(256) void rmsnorm_kernel(float* __restrict__ x,
                                                      const float* __restrict__ w, int n) {
    __shared__ float sh[33];
    int row = blockIdx.x, t = threadIdx.x;
    float* p = x + (size_t)row * n;
    int cnt = n / 256;
    float local[8];
    float ss = 0.f;
    for (int i = 0; i < cnt; i++) { float v = p[t + i * 256]; local[i] = v; ss += v * v; }
    float total = blockReduceSum(ss, sh);
    float scale = rsqrtf(total / (float)n + EPS_);
    for (int i = 0; i < cnt; i++) p[t + i * 256] = local[i] * scale * w[t + i * 256];
}

// ---------------- ckv split (reads extended row; kpe stored fp16) ----------------
__global__ __launch_bounds__(256) void ckv_split_kernel(const float* __restrict__ w) {
    __shared__ float sh[33];
    int s = blockIdx.x, t = threadIdx.x;
    const float* p = g_ckvx + (size_t)s * CKVX_;
    float v0 = p[t], v1 = p[256 + t];
    float total = blockReduceSum(v0 * v0 + v1 * v1, sh);
    float scale = rsqrtf(total / (float)KVR_ + EPS_);
    g_ckvn[(size_t)s * KVR_ + t] = v0 * scale * w[t];
    g_ckvn[(size_t)s * KVR_ + 256 + t] = v1 * scale * w[256 + t];
    if (t < 32) {
        float x1 = p[KVR_ + t], x2 = p[KVR_ + 32 + t];
        float c = g_cosb[s * 32 + t], sn = g_sinb[s * 32 + t];
        g_kpeh[s * ROPE_ + t]      = __float2half_rn(x1 * c - x2 * sn);
        g_kpeh[s * ROPE_ + 32 + t] = __float2half_rn(x2 * c + x1 * sn);
    }
}

// ---------------- layernorm + rope for ik ----------------
__global__ __launch_bounds__(128) void ik_ln_rope_kernel(const float* __restrict__ xin,
                                                         const float* __restrict__ w,
                                                         const float* __restrict__ b) {
    __shared__ float sh[33];
    __shared__ float sn_[128];
    int s = blockIdx.x, t = threadIdx.x;
    float x = xin[(size_t)s * ID_ + t];
    float mean = blockReduceSum(x, sh) / (float)ID_;
    float var = blockReduceSum(x * x, sh) / (float)ID_ - mean * mean;
    float nv = (x - mean) * rsqrtf(var + EPS_) * w[t] + b[t];
    sn_[t] = nv;
    __syncthreads();
    float out;
    if (t < 32) {
        float c = g_cosb[s * 32 + t], snv = g_sinb[s * 32 + t];
        out = sn_[t] * c - sn_[t + 32] * snv;
    } else if (t < 64) {
        float c = g_cosb[s * 32 + (t - 32)], snv = g_sinb[s * 32 + (t - 32)];
        out = sn_[t] * c + sn_[t - 32] * snv;
    } else {
        out = nv;
    }
    g_ik[(size_t)s * ID_ + t] = out;
}

// ---------------- generic in-place rope over heads ----------------
__global__ void rope_kernel(float* __restrict__ base, int rowStride, int headStride) {
    int s = blockIdx.x;
    int h = threadIdx.y, d = threadIdx.x;
    float* p = base + (size_t)s * rowStride + h * headStride;
    float c = g_cosb[s * 32 + d], sn = g_sinb[s * 32 + d];
    float x1 = p[d], x2 = p[d + 32];
    p[d] = x1 * c - x2 * sn;
    p[d + 32] = x2 * c + x1 * sn;
}

// ============ fused indexer w/ FFMA2 + causal skip (iw from g_ckvx col 576+h) ============
__global__ __launch_bounds__(256, 2) void idx_scores_kernel() {
    int m0 = blockIdx.y * 128, n0 = blockIdx.x * 64;
    int t = threadIdx.x;
    int tx = t & 15, ty = t >> 4;
    const float NINF = __int_as_float(0xff800000);

    if (m0 + 128 <= TOPK_) return;
    if (n0 >= m0 + 128) {
        #pragma unroll
        for (int i = 0; i < 8; i++) {
            int gm = m0 + ty * 8 + i;
            #pragma unroll
            for (int j = 0; j < 4; j++)
                g_scores[(size_t)gm * S_ + n0 + tx * 4 + j] = NINF;
        }
        return;
    }

    __shared__ float Bs[128][64];
    __shared__ float As[2][8][128];
    int a_m = t >> 1, a_k = (t & 1) * 4;

    for (int i = t; i < 64 * 32; i += 256) {
        int nl = i >> 5, k4 = (i & 31) * 4;
        float4 v = *reinterpret_cast<const float4*>(&g_ik[(size_t)(n0 + nl) * ID_ + k4]);
        Bs[k4+0][nl] = v.x; Bs[k4+1][nl] = v.y; Bs[k4+2][nl] = v.z; Bs[k4+3][nl] = v.w;
    }

    float sacc[8][4];
    #pragma unroll
    for (int i = 0; i < 8; i++)
        #pragma unroll
        for (int j = 0; j < 4; j++) sacc[i][j] = 0.f;
    __syncthreads();

    const size_t lda = IH_ * ID_;
    for (int h = 0; h < IH_; h++) {
        const float* A = g_iq + (size_t)h * ID_ + (size_t)(m0 + a_m) * lda;
        {
            float4 v = *reinterpret_cast<const float4*>(&A[a_k]);
            As[0][a_k+0][a_m]=v.x; As[0][a_k+1][a_m]=v.y; As[0][a_k+2][a_m]=v.z; As[0][a_k+3][a_m]=v.w;
        }
        __syncthreads();
        u64 tacc[8][2];
        #pragma unroll
        for (int i = 0; i < 8; i++) { tacc[i][0] = 0ull; tacc[i][1] = 0ull; }
        int buf = 0;
        for (int k0 = 0; k0 < 128; k0 += 8) {
            float4 v;
            bool nxt = (k0 + 8) < 128;
            if (nxt) v = *reinterpret_cast<const float4*>(&A[k0 + 8 + a_k]);
            #pragma unroll
            for (int k = 0; k < 8; k++) {
                float4 a0 = *reinterpret_cast<const float4*>(&As[buf][k][ty * 8]);
                float4 a1 = *reinterpret_cast<const float4*>(&As[buf][k][ty * 8 + 4]);
                float4 b0 = *reinterpret_cast<const float4*>(&Bs[k0 + k][tx * 4]);
                u64 bb[2] = {pack2(b0.x,b0.y), pack2(b0.z,b0.w)};
                float ra[8] = {a0.x,a0.y,a0.z,a0.w,a1.x,a1.y,a1.z,a1.w};
                #pragma unroll
                for (int i = 0; i < 8; i++) {
                    u64 aa = pack2(ra[i], ra[i]);
                    ffma2(tacc[i][0], aa, bb[0]);
                    ffma2(tacc[i][1], aa, bb[1]);
                }
            }
            if (nxt) {
                int nb = buf ^ 1;
                As[nb][a_k+0][a_m]=v.x; As[nb][a_k+1][a_m]=v.y; As[nb][a_k+2][a_m]=v.z; As[nb][a_k+3][a_m]=v.w;
                __syncthreads();
                buf = nb;
            }
        }
        __syncthreads();
        #pragma unroll
        for (int i = 0; i < 8; i++) {
            float w = g_ckvx[(size_t)(m0 + ty * 8 + i) * CKVX_ + 576 + h];
            float2 t01 = unpack2(tacc[i][0]);
            float2 t23 = unpack2(tacc[i][1]);
            float tv[4] = {t01.x, t01.y, t23.x, t23.y};
            #pragma unroll
            for (int j = 0; j < 4; j++) {
                float add = __fmul_rn(w, fmaxf(tv[j], 0.f));
                sacc[i][j] = __fadd_rn(sacc[i][j], add);
            }
        }
    }
    #pragma unroll
    for (int i = 0; i < 8; i++) {
        int gm = m0 + ty * 8 + i;
        #pragma unroll
        for (int j = 0; j < 4; j++) {
            int gn = n0 + tx * 4 + j;
            g_scores[(size_t)gm * S_ + gn] = (gn <= gm) ? sacc[i][j] : NINF;
        }
    }
}

// ---------------- top-k (stable, jax tie semantics) ----------------
__device__ __forceinline__ unsigned fkey(float f) {
    unsigned u = __float_as_uint(f);
    return u ^ ((u >> 31) ? 0xFFFFFFFFu : 0x80000000u);
}

__global__ __launch_bounds__(256) void topk_kernel() {
    int q = blockIdx.x, t = threadIdx.x;
    const float* sc = g_scores + (size_t)q * S_;
    if (q < TOPK_) {
        for (int i = t; i <= q; i += 256) g_sel[(size_t)q * TOPK_ + i] = i;
        if (t == 0) g_nsel[q] = q + 1;
        return;
    }
    __shared__ unsigned hist[256];
    __shared__ unsigned s_pref, s_r;
    __shared__ int s_gt[257], s_eq[257];

    unsigned pref = 0, r = TOPK_;
    #pragma unroll
    for (int p = 3; p >= 0; p--) {
        hist[t] = 0;
        __syncthreads();
        for (int i = t; i < S_; i += 256) {
            unsigned u = fkey(sc[i]);
            bool ok = (p == 3) || ((u >> ((p + 1) * 8)) == pref);
            if (ok) atomicAdd(&hist[(u >> (p * 8)) & 255], 1u);
        }
        __syncthreads();
        if (t == 0) {
            unsigned run = 0;
            int b = 255;
            for (; b >= 0; b--) {
                unsigned c = hist[b];
                if (run + c >= r) break;
                run += c;
            }
            s_pref = (pref << 8) | (unsigned)b;
            s_r = r - run;
        }
        __syncthreads();
        pref = s_pref; r = s_r;
        __syncthreads();
    }
    unsigned T = pref;
    int need_eq = (int)r;

    int i0 = t * 8;
    unsigned keys[8];
    int cg = 0, ce = 0;
    #pragma unroll
    for (int k = 0; k < 8; k++) {
        unsigned u = fkey(sc[i0 + k]);
        keys[k] = u;
        cg += (u > T);
        ce += (u == T);
    }
    s_gt[t] = cg; s_eq[t] = ce;
    __syncthreads();
    if (t == 0) {
        int rg = 0, re = 0;
        for (int i = 0; i < 256; i++) {
            int a = s_gt[i]; s_gt[i] = rg; rg += a;
            int b2 = s_eq[i]; s_eq[i] = re; re += b2;
        }
        s_gt[256] = rg;
    }
    __syncthreads();
    int gpos = s_gt[t], epos = s_eq[t], total_gt = s_gt[256];
    int* out = g_sel + (size_t)q * TOPK_;
    #pragma unroll
    for (int k = 0; k < 8; k++) {
        unsigned u = keys[k];
        if (u > T) out[gpos++] = i0 + k;
        else if (u == T) {
            if (epos < need_eq) out[total_gt + epos] = i0 + k;
            epos++;
        }
    }
    if (t == 0) g_nsel[q] = TOPK_;
}

// ---------------- sparse attention (round-11 shape; fp16 KV + fp16 kpe, fp32 math) --------
__global__ __launch_bounds__(128) void sparse_attn_kernel() {
    const float SCALE = 0.07216878364870322f;
    int qi = blockIdx.x, h = blockIdx.y;
    int t = threadIdx.x, w = t >> 5, lane = t & 31;
    __shared__ float qv[192];
    __shared__ float s_p[TOPK_];
    __shared__ int s_idx[TOPK_];
    __shared__ float s_red[4];
    __shared__ float s_out[4][128];

    int n = g_nsel[qi];
    const float* qptr = g_q + (size_t)qi * (H_ * 192) + h * 192;
    for (int i = t; i < 192; i += 128) qv[i] = qptr[i];
    for (int i = t; i < n; i += 128) s_idx[i] = g_sel[(size_t)qi * TOPK_ + i];
    __syncthreads();

    for (int j = w; j < n; j += 4) {
        int kidx = s_idx[j];
        const __half* kh = g_kvh + (size_t)kidx * (H_ * 256) + h * 256;
        uint2 raw = *reinterpret_cast<const uint2*>(kh + lane * 4);
        float2 f01 = __half22float2(*reinterpret_cast<const __half2*>(&raw.x));
        float2 f23 = __half22float2(*reinterpret_cast<const __half2*>(&raw.y));
        float4 a = reinterpret_cast<const float4*>(qv)[lane];
        float d = a.x * f01.x + a.y * f01.y + a.z * f23.x + a.w * f23.y;
        unsigned rawp = *reinterpret_cast<const unsigned*>(g_kpeh + (size_t)kidx * ROPE_ + lane * 2);
        float2 bp = __half22float2(*reinterpret_cast<const __half2*>(&rawp));
        float2 ap = reinterpret_cast<const float2*>(qv + 128)[lane];
        d += ap.x * bp.x + ap.y * bp.y;
        #pragma unroll
        for (int o = 16; o; o >>= 1) d += __shfl_down_sync(0xffffffffu, d, o);
        if (lane == 0) s_p[j] = d * SCALE;
    }
    __syncthreads();

    float m = -3.4e38f;
    for (int i = t; i < n; i += 128) m = fmaxf(m, s_p[i]);
    #pragma unroll
    for (int o = 16; o; o >>= 1) m = fmaxf(m, __shfl_xor_sync(0xffffffffu, m, o));
    if (lane == 0) s_red[w] = m;
    __syncthreads();
    m = fmaxf(fmaxf(s_red[0], s_red[1]), fmaxf(s_red[2], s_red[3]));
    __syncthreads();

    float sum = 0.f;
    for (int i = t; i < n; i += 128) {
        float e = __expf(s_p[i] - m);
        s_p[i] = e;
        sum += e;
    }
    #pragma unroll
    for (int o = 16; o; o >>= 1) sum += __shfl_xor_sync(0xffffffffu, sum, o);
    __syncthreads();
    if (lane == 0) s_red[w] = sum;
    __syncthreads();
    sum = s_red[0] + s_red[1] + s_red[2] + s_red[3];
    float inv = 1.0f / sum;

    float4 acc = make_float4(0.f, 0.f, 0.f, 0.f);
    for (int j = w; j < n; j += 4) {
        float p = s_p[j];
        int kidx = s_idx[j];
        const __half* vh = g_kvh + (size_t)kidx * (H_ * 256) + h * 256 + 128;
        uint2 raw = *reinterpret_cast<const uint2*>(vh + lane * 4);
        float2 v01 = __half22float2(*reinterpret_cast<const __half2*>(&raw.x));
        float2 v23 = __half22float2(*reinterpret_cast<const __half2*>(&raw.y));
        acc.x += p * v01.x; acc.y += p * v01.y; acc.z += p * v23.x; acc.w += p * v23.y;
    }
    reinterpret_cast<float4*>(&s_out[w][0])[lane] = acc;
    __syncthreads();
    float o = (s_out[0][t] + s_out[1][t] + s_out[2][t] + s_out[3][t]) * inv;
    g_attn[(size_t)qi * (H_ * VDIM_) + h * VDIM_ + t] = o;
}

// ---------------- launch ----------------
extern "C" void kernel_launch(void* const* d_in, const int* in_sizes, int n_in,
                              void* d_out, int out_size) {
    (void)in_sizes; (void)n_in; (void)out_size;
    const float* hidden      = (const float*)d_in[0];
    const float* q_a_w       = (const float*)d_in[1];
    const float* q_a_ln_w    = (const float*)d_in[2];
    const float* q_b_w       = (const float*)d_in[3];
    const float* kv_a_w      = (const float*)d_in[4];
    const float* kv_a_ln_w   = (const float*)d_in[5];
    const float* kv_b_w      = (const float*)d_in[6];
    const float* o_w         = (const float*)d_in[7];
    const float* idx_wq_b_w  = (const float*)d_in[8];
    const float* idx_wk_w    = (const float*)d_in[9];
    const float* idx_kn_w    = (const float*)d_in[10];
    const float* idx_kn_b    = (const float*)d_in[11];
    const float* idx_wproj_w = (const float*)d_in[12];
    float* out = (float*)d_out;

    float *p_qr, *p_q, *p_iq, *p_ikpre, *p_attn;
    cudaGetSymbolAddress((void**)&p_qr,    g_qr);
    cudaGetSymbolAddress((void**)&p_q,     g_q);
    cudaGetSymbolAddress((void**)&p_iq,    g_iq);
    cudaGetSymbolAddress((void**)&p_ikpre, g_ikpre);
    cudaGetSymbolAddress((void**)&p_attn,  g_attn);

    dim3 tb(256);

    cossin_kernel<<<S_, 32>>>();
    build_bext_kernel<<<(CKVX_ * HID_ / 4 + 255) / 256, 256>>>(kv_a_w, idx_wproj_w);

    // qr | ckvx(incl 0.25*iw) | ik — 288 blocks, single wave over A=hidden (K=2048)
    fused_hidden_gemm<<<dim3(18, S_ / 128), tb>>>(hidden, q_a_w, idx_wk_w);
    rmsnorm_kernel<<<S_, 256>>>(p_qr, q_a_ln_w, QR_);
    ckv_split_kernel<<<S_, 256>>>(kv_a_ln_w);
    ik_ln_rope_kernel<<<S_, 128>>>(p_ikpre, idx_kn_w, idx_kn_b);

    // q | iq (K=1536) with kv_b (K=512, fp16 out) backfilling the tail wave
    fused_qr_kv_gemm<<<dim3(72, S_ / 128), tb>>>(q_b_w, idx_wq_b_w, kv_b_w);

    // rope q_pe and iq
    rope_kernel<<<S_, dim3(32, H_)>>>(p_q + NOPE_, H_ * 192, 192);
    rope_kernel<<<S_, dim3(32, IH_)>>>(p_iq, IH_ * ID_, ID_);

    // fused indexer scores (causal skip + FFMA2)
    idx_scores_kernel<<<dim3(S_ / 64, S_ / 128), tb>>>();

    topk_kernel<<<S_, 256>>>();

    sparse_attn_kernel<<<dim3(S_, H_), 128>>>();

    // out = attn @ o_w^T   [S, 2048]
    sgemm_nt_db<<<dim3(HID_ / 128, S_ / 128), tb>>>(p_attn, H_ * VDIM_, o_w, H_ * VDIM_, out, HID_, S_, HID_, H_ * VDIM_, 1.f);
}

// round 14
// speedup vs baseline: 1.4256x; 1.3750x over previous
#include <cuda_runtime.h>
#include <cuda_fp16.h>
#include <math.h>

#define S_    2048
#define HID_  2048
#define H_    16
#define NOPE_ 128
#define ROPE_ 64
#define VDIM_ 128
#define QR_   1536
#define KVR_  512
#define IH_   16
#define ID_   128
#define TOPK_ 512
#define EPS_  1e-6f
#define CKVX_ 640          // extended ckv row: 512 ckv | 64 kpe-src | 16 iw | 48 pad

typedef unsigned long long u64;

// ---------------- packed f32x2 helpers (bit-identical to two scalar FFMAs) ----------------
__device__ __forceinline__ void ffma2(u64 &d, u64 a, u64 b) {
    asm("fma.rn.f32x2 %0, %1, %2, %0;" : "+l"(d) : "l"(a), "l"(b));
}
__device__ __forceinline__ u64 pack2(float lo, float hi) {
    u64 r; asm("mov.b64 %0, {%1, %2};" : "=l"(r) : "f"(lo), "f"(hi)); return r;
}
__device__ __forceinline__ float2 unpack2(u64 v) {
    float2 r; asm("mov.b64 {%0, %1}, %2;" : "=f"(r.x), "=f"(r.y) : "l"(v)); return r;
}
__device__ __forceinline__ unsigned sptr(const void* p) {
    return (unsigned)__cvta_generic_to_shared(p);
}

// ---------------- scratch ----------------
__device__ float  g_qr    [S_*QR_];
__device__ __half g_qrh   [S_*QR_];
__device__ float  g_q     [S_*H_*(NOPE_+ROPE_)];
__device__ float  g_ckvx  [S_*CKVX_];
__device__ float  g_bext  [CKVX_*HID_];
__device__ __half g_ckvnh [S_*KVR_];
__device__ __half g_kpeh  [S_*ROPE_];
__device__ __half g_kvh   [S_*H_*(NOPE_+VDIM_)];
__device__ float  g_iq    [S_*IH_*ID_];
__device__ float  g_ikpre [S_*ID_];
__device__ float  g_ik    [S_*ID_];
__device__ float  g_scores[S_*S_];
__device__ int    g_sel   [S_*TOPK_];
__device__ int    g_nsel  [S_];
__device__ __half g_attnh [S_*H_*VDIM_];
__device__ __half g_qbwh  [(H_*192)*QR_];
__device__ __half g_kvbwh [(H_*256)*KVR_];
__device__ __half g_owh   [HID_*(H_*VDIM_)];
__device__ float  g_cosb  [S_*32];
__device__ float  g_sinb  [S_*32];

// ---------------- helpers ----------------
__device__ __forceinline__ float blockReduceSum(float v, float* sh) {
    int lane = threadIdx.x & 31, w = threadIdx.x >> 5;
    #pragma unroll
    for (int o = 16; o; o >>= 1) v += __shfl_xor_sync(0xffffffffu, v, o);
    if (lane == 0) sh[w] = v;
    __syncthreads();
    int nw = (blockDim.x + 31) >> 5;
    float r = (threadIdx.x < nw) ? sh[threadIdx.x] : 0.f;
    if (w == 0) {
        #pragma unroll
        for (int o = 16; o; o >>= 1) r += __shfl_xor_sync(0xffffffffu, r, o);
        if (lane == 0) sh[0] = r;
    }
    __syncthreads();
    float out = sh[0];
    __syncthreads();
    return out;
}

// ---------------- cos/sin (bit-exact numpy float32 path) ----------------
__global__ void cossin_kernel() {
    int s = blockIdx.x, d = threadIdx.x;
    float e = (float)(2 * d) / 64.0f;
    float pf = (float)pow(10000.0, (double)e);
    float inv = __fdiv_rn(1.0f, pf);
    float f = __fmul_rn((float)s, inv);
    g_cosb[s * 32 + d] = (float)cos((double)f);
    g_sinb[s * 32 + d] = (float)sin((double)f);
}

// ---------------- fp32 -> fp16 conversion ----------------
__global__ __launch_bounds__(256) void f2h_kernel(const float* __restrict__ src,
                                                  __half* __restrict__ dst, int n4) {
    int i = blockIdx.x * 256 + threadIdx.x;
    if (i < n4) {
        float4 v = reinterpret_cast<const float4*>(src)[i];
        reinterpret_cast<__half2*>(dst)[i * 2]     = __floats2half2_rn(v.x, v.y);
        reinterpret_cast<__half2*>(dst)[i * 2 + 1] = __floats2half2_rn(v.z, v.w);
    }
}

// ---------------- build extended B slab: kv_a_w | 0.25*idx_wproj_w | zeros ----------------
__global__ __launch_bounds__(256) void build_bext_kernel(
    const float* __restrict__ kv_a_w, const float* __restrict__ idx_wproj_w)
{
    size_t idx = (size_t)blockIdx.x * 256 + threadIdx.x;
    size_t row = idx / (HID_ / 4), c4 = idx % (HID_ / 4);
    float4 v;
    if (row < 576) {
        v = reinterpret_cast<const float4*>(kv_a_w)[row * (HID_ / 4) + c4];
    } else if (row < 592) {
        v = reinterpret_cast<const float4*>(idx_wproj_w)[(row - 576) * (HID_ / 4) + c4];
        v.x *= 0.25f; v.y *= 0.25f; v.z *= 0.25f; v.w *= 0.25f;
    } else {
        v = make_float4(0.f, 0.f, 0.f, 0.f);
    }
    reinterpret_cast<float4*>(g_bext)[idx] = v;
}

// ============ fp32 GEMM body (indexer-critical path): 128x128, quadrant, FFMA2 ============
__device__ __forceinline__ void gemm_body_128(
    const float* __restrict__ A, int lda,
    const float* __restrict__ B, int ldb,
    float* __restrict__ C, int ldc,
    int M, int N, int K, float alpha,
    int m0, int n0,
    float (*As)[8][128], float (*Bs)[8][128])
{
    int t = threadIdx.x;
    int tx = t & 15, ty = t >> 4;
    int a_m = t >> 1, a_k = (t & 1) * 4;
    int gmA = m0 + a_m, gnB = n0 + a_m;
    u64 acc[8][4];
    #pragma unroll
    for (int i = 0; i < 8; i++)
        #pragma unroll
        for (int j = 0; j < 4; j++) acc[i][j] = 0ull;

    float4 va = make_float4(0.f,0.f,0.f,0.f), vb = va;
    if (gmA < M) va = *reinterpret_cast<const float4*>(&A[(size_t)gmA * lda + a_k]);
    if (gnB < N) vb = *reinterpret_cast<const float4*>(&B[(size_t)gnB * ldb + a_k]);
    As[0][a_k+0][a_m]=va.x; As[0][a_k+1][a_m]=va.y; As[0][a_k+2][a_m]=va.z; As[0][a_k+3][a_m]=va.w;
    Bs[0][a_k+0][a_m]=vb.x; Bs[0][a_k+1][a_m]=vb.y; Bs[0][a_k+2][a_m]=vb.z; Bs[0][a_k+3][a_m]=vb.w;
    __syncthreads();
    int buf = 0;
    for (int k0 = 0; k0 < K; k0 += 8) {
        bool nxt = (k0 + 8) < K;
        if (nxt) {
            va = make_float4(0.f,0.f,0.f,0.f); vb = va;
            if (gmA < M) va = *reinterpret_cast<const float4*>(&A[(size_t)gmA * lda + k0 + 8 + a_k]);
            if (gnB < N) vb = *reinterpret_cast<const float4*>(&B[(size_t)gnB * ldb + k0 + 8 + a_k]);
        }
        #pragma unroll
        for (int k = 0; k < 8; k++) {
            float4 a0 = *reinterpret_cast<const float4*>(&As[buf][k][ty * 4]);
            float4 a1 = *reinterpret_cast<const float4*>(&As[buf][k][64 + ty * 4]);
            float4 b0 = *reinterpret_cast<const float4*>(&Bs[buf][k][tx * 4]);
            float4 b1 = *reinterpret_cast<const float4*>(&Bs[buf][k][64 + tx * 4]);
            u64 bb[4] = {pack2(b0.x,b0.y), pack2(b0.z,b0.w), pack2(b1.x,b1.y), pack2(b1.z,b1.w)};
            float ra[8] = {a0.x,a0.y,a0.z,a0.w,a1.x,a1.y,a1.z,a1.w};
            #pragma unroll
            for (int i = 0; i < 8; i++) {
                u64 aa = pack2(ra[i], ra[i]);
                #pragma unroll
                for (int j = 0; j < 4; j++) ffma2(acc[i][j], aa, bb[j]);
            }
        }
        if (nxt) {
            int nb = buf ^ 1;
            As[nb][a_k+0][a_m]=va.x; As[nb][a_k+1][a_m]=va.y; As[nb][a_k+2][a_m]=va.z; As[nb][a_k+3][a_m]=va.w;
            Bs[nb][a_k+0][a_m]=vb.x; Bs[nb][a_k+1][a_m]=vb.y; Bs[nb][a_k+2][a_m]=vb.z; Bs[nb][a_k+3][a_m]=vb.w;
            __syncthreads();
            buf = nb;
        }
    }
    #pragma unroll
    for (int i = 0; i < 8; i++) {
        int gm = m0 + ((i < 4) ? (ty * 4 + i) : (64 + ty * 4 + i - 4));
        if (gm >= M) continue;
        #pragma unroll
        for (int j = 0; j < 4; j++) {
            float2 v = unpack2(acc[i][j]);
            int gn = n0 + ((j < 2) ? (tx * 4 + j * 2) : (64 + tx * 4 + (j - 2) * 2));
            if (gn < N)     C[(size_t)gm * ldc + gn]     = alpha * v.x;
            if (gn + 1 < N) C[(size_t)gm * ldc + gn + 1] = alpha * v.y;
        }
    }
}

__global__ __launch_bounds__(256, 2) void sgemm_nt_db(
    const float* __restrict__ A, int lda,
    const float* __restrict__ B, int ldb,
    float* __restrict__ C, int ldc,
    int M, int N, int K, float alpha)
{
    __shared__ float As[2][8][128];
    __shared__ float Bs[2][8][128];
    gemm_body_128(A, lda, B, ldb, C, ldc, M, N, K, alpha,
                  blockIdx.y * 128, blockIdx.x * 128, As, Bs);
}

// ---------------- fused A=hidden (K=2048): qr | ckvx(incl iw) | ik — 288 blocks ----------------
__global__ __launch_bounds__(256, 2) void fused_hidden_gemm(
    const float* __restrict__ A,
    const float* __restrict__ Bqr, const float* __restrict__ Bik)
{
    __shared__ float As[2][8][128];
    __shared__ float Bs[2][8][128];
    int bx = blockIdx.x;
    const float* B; float* C; int N, ldc, n0;
    if (bx < 12)      { B = Bqr;    C = g_qr;    N = QR_;   ldc = QR_;   n0 = bx * 128; }
    else if (bx < 17) { B = g_bext; C = g_ckvx;  N = CKVX_; ldc = CKVX_; n0 = (bx - 12) * 128; }
    else              { B = Bik;    C = g_ikpre; N = ID_;   ldc = ID_;   n0 = 0; }
    gemm_body_128(A, HID_, B, HID_, C, ldc, S_, N, HID_, 1.f,
                  blockIdx.y * 128, n0, As, Bs);
}

// ============ fp16 tensor-core GEMM: C[M,N] = A[M,K] @ B[N,K]^T (fp32 accumulate) ============
// 128x128 tile, 8 warps (2m x 4n), warp tile 64x32, mma.m16n8k16. Full tiles only.
__global__ __launch_bounds__(256, 2) void hgemm_nt(
    const __half* __restrict__ A, int lda,
    const __half* __restrict__ B, int ldb,
    void* __restrict__ Cv, int ldc,
    int K, int halfOut)
{
    __shared__ __half As[2][128][24];   // stride 24 halves: conflict-free ldmatrix
    __shared__ __half Bs[2][128][24];
    int t = threadIdx.x;
    int lane = t & 31, wid = t >> 5;
    int wm = (wid & 1) * 64, wn = (wid >> 1) * 32;
    int m0 = blockIdx.y * 128, n0 = blockIdx.x * 128;
    int l_r = t >> 1, l_c = (t & 1) * 8;

    float acc[4][4][4];
    #pragma unroll
    for (int i = 0; i < 4; i++)
        #pragma unroll
        for (int j = 0; j < 4; j++)
            #pragma unroll
            for (int c = 0; c < 4; c++) acc[i][j][c] = 0.f;

    uint4 va = *reinterpret_cast<const uint4*>(&A[(size_t)(m0 + l_r) * lda + l_c]);
    uint4 vb = *reinterpret_cast<const uint4*>(&B[(size_t)(n0 + l_r) * ldb + l_c]);
    *reinterpret_cast<uint4*>(&As[0][l_r][l_c]) = va;
    *reinterpret_cast<uint4*>(&Bs[0][l_r][l_c]) = vb;
    __syncthreads();

    int a_row = lane & 15, a_col = (lane >> 4) * 8;           // ldmatrix.x4 lane map
    int b_row = lane & 7,  b_col = ((lane >> 3) & 1) * 8;     // ldmatrix.x2 lane map

    int buf = 0;
    for (int k0 = 0; k0 < K; k0 += 16) {
        bool nxt = (k0 + 16) < K;
        if (nxt) {
            va = *reinterpret_cast<const uint4*>(&A[(size_t)(m0 + l_r) * lda + k0 + 16 + l_c]);
            vb = *reinterpret_cast<const uint4*>(&B[(size_t)(n0 + l_r) * ldb + k0 + 16 + l_c]);
        }
        unsigned af[4][4], bf[4][2];
        #pragma unroll
        for (int i = 0; i < 4; i++) {
            unsigned addr = sptr(&As[buf][wm + 16 * i + a_row][a_col]);
            asm volatile("ldmatrix.sync.aligned.m8n8.x4.shared.b16 {%0,%1,%2,%3}, [%4];"
                : "=r"(af[i][0]), "=r"(af[i][1]), "=r"(af[i][2]), "=r"(af[i][3]) : "r"(addr));
        }
        #pragma unroll
        for (int j = 0; j < 4; j++) {
            unsigned addr = sptr(&Bs[buf][wn + 8 * j + b_row][b_col]);
            asm volatile("ldmatrix.sync.aligned.m8n8.x2.shared.b16 {%0,%1}, [%2];"
                : "=r"(bf[j][0]), "=r"(bf[j][1]) : "r"(addr));
        }
        #pragma unroll
        for (int i = 0; i < 4; i++)
            #pragma unroll
            for (int j = 0; j < 4; j++)
                asm volatile("mma.sync.aligned.m16n8k16.row.col.f32.f16.f16.f32 "
                    "{%0,%1,%2,%3}, {%4,%5,%6,%7}, {%8,%9}, {%0,%1,%2,%3};"
                    : "+f"(acc[i][j][0]), "+f"(acc[i][j][1]), "+f"(acc[i][j][2]), "+f"(acc[i][j][3])
                    : "r"(af[i][0]), "r"(af[i][1]), "r"(af[i][2]), "r"(af[i][3]),
                      "r"(bf[j][0]), "r"(bf[j][1]));
        if (nxt) {
            int nb = buf ^ 1;
            *reinterpret_cast<uint4*>(&As[nb][l_r][l_c]) = va;
            *reinterpret_cast<uint4*>(&Bs[nb][l_r][l_c]) = vb;
            __syncthreads();
            buf = nb;
        }
    }

    int r = lane >> 2, cpair = (lane & 3) * 2;
    #pragma unroll
    for (int i = 0; i < 4; i++) {
        int gm0 = m0 + wm + 16 * i + r;
        #pragma unroll
        for (int j = 0; j < 4; j++) {
            int gn = n0 + wn + 8 * j + cpair;
            if (halfOut) {
                __half* C = reinterpret_cast<__half*>(Cv);
                *reinterpret_cast<__half2*>(&C[(size_t)gm0 * ldc + gn]) =
                    __floats2half2_rn(acc[i][j][0], acc[i][j][1]);
                *reinterpret_cast<__half2*>(&C[(size_t)(gm0 + 8) * ldc + gn]) =
                    __floats2half2_rn(acc[i][j][2], acc[i][j][3]);
            } else {
                float* C = reinterpret_cast<float*>(Cv);
                C[(size_t)gm0 * ldc + gn]         = acc[i][j][0];
                C[(size_t)gm0 * ldc + gn + 1]     = acc[i][j][1];
                C[(size_t)(gm0 + 8) * ldc + gn]     = acc[i][j][2];
                C[(size_t)(gm0 + 8) * ldc + gn + 1] = acc[i][j][3];
            }
        }
    }
}

// ---------------- rmsnorm (in-place fp32 + fp16 copy for HMMA) ----------------
__global__ __launch_bounds__(256) void rmsnorm_kernel(float* __restrict__ x,
                                                      __half* __restrict__ xh,
                                                      const float* __restrict__ w, int n) {
    __shared__ float sh[33];
    int row = blockIdx.x, t = threadIdx.x;
    float* p = x + (size_t)row * n;
    int cnt = n / 256;
    float local[8];
    float ss = 0.f;
    for (int i = 0; i < cnt; i++) { float v = p[t + i * 256]; local[i] = v; ss += v * v; }
    float total = blockReduceSum(ss, sh);
    float scale = rsqrtf(total / (float)n + EPS_);
    for (int i = 0; i < cnt; i++) {
        float o = local[i] * scale * w[t + i * 256];
        p[t + i * 256] = o;
        xh[(size_t)row * n + t + i * 256] = __float2half_rn(o);
    }
}

// ---------------- ckv split (ckvn stored fp16; kpe fp16) ----------------
__global__ __launch_bounds__(256) void ckv_split_kernel(const float* __restrict__ w) {
    __shared__ float sh[33];
    int s = blockIdx.x, t = threadIdx.x;
    const float* p = g_ckvx + (size_t)s * CKVX_;
    float v0 = p[t], v1 = p[256 + t];
    float total = blockReduceSum(v0 * v0 + v1 * v1, sh);
    float scale = rsqrtf(total / (float)KVR_ + EPS_);
    g_ckvnh[(size_t)s * KVR_ + t]       = __float2half_rn(v0 * scale * w[t]);
    g_ckvnh[(size_t)s * KVR_ + 256 + t] = __float2half_rn(v1 * scale * w[256 + t]);
    if (t < 32) {
        float x1 = p[KVR_ + t], x2 = p[KVR_ + 32 + t];
        float c = g_cosb[s * 32 + t], sn = g_sinb[s * 32 + t];
        g_kpeh[s * ROPE_ + t]      = __float2half_rn(x1 * c - x2 * sn);
        g_kpeh[s * ROPE_ + 32 + t] = __float2half_rn(x2 * c + x1 * sn);
    }
}

// ---------------- layernorm + rope for ik ----------------
__global__ __launch_bounds__(128) void ik_ln_rope_kernel(const float* __restrict__ xin,
                                                         const float* __restrict__ w,
                                                         const float* __restrict__ b) {
    __shared__ float sh[33];
    __shared__ float sn_[128];
    int s = blockIdx.x, t = threadIdx.x;
    float x = xin[(size_t)s * ID_ + t];
    float mean = blockReduceSum(x, sh) / (float)ID_;
    float var = blockReduceSum(x * x, sh) / (float)ID_ - mean * mean;
    float nv = (x - mean) * rsqrtf(var + EPS_) * w[t] + b[t];
    sn_[t] = nv;
    __syncthreads();
    float out;
    if (t < 32) {
        float c = g_cosb[s * 32 + t], snv = g_sinb[s * 32 + t];
        out = sn_[t] * c - sn_[t + 32] * snv;
    } else if (t < 64) {
        float c = g_cosb[s * 32 + (t - 32)], snv = g_sinb[s * 32 + (t - 32)];
        out = sn_[t] * c + sn_[t - 32] * snv;
    } else {
        out = nv;
    }
    g_ik[(size_t)s * ID_ + t] = out;
}

// ---------------- generic in-place rope over heads ----------------
__global__ void rope_kernel(float* __restrict__ base, int rowStride, int headStride) {
    int s = blockIdx.x;
    int h = threadIdx.y, d = threadIdx.x;
    float* p = base + (size_t)s * rowStride + h * headStride;
    float c = g_cosb[s * 32 + d], sn = g_sinb[s * 32 + d];
    float x1 = p[d], x2 = p[d + 32];
    p[d] = x1 * c - x2 * sn;
    p[d + 32] = x2 * c + x1 * sn;
}

// ============ fused indexer w/ FFMA2 + causal skip (iw from g_ckvx col 576+h) ============
__global__ __launch_bounds__(256, 2) void idx_scores_kernel() {
    int m0 = blockIdx.y * 128, n0 = blockIdx.x * 64;
    int t = threadIdx.x;
    int tx = t & 15, ty = t >> 4;
    const float NINF = __int_as_float(0xff800000);

    if (m0 + 128 <= TOPK_) return;
    if (n0 >= m0 + 128) {
        #pragma unroll
        for (int i = 0; i < 8; i++) {
            int gm = m0 + ty * 8 + i;
            #pragma unroll
            for (int j = 0; j < 4; j++)
                g_scores[(size_t)gm * S_ + n0 + tx * 4 + j] = NINF;
        }
        return;
    }

    __shared__ float Bs[128][64];
    __shared__ float As[2][8][128];
    int a_m = t >> 1, a_k = (t & 1) * 4;

    for (int i = t; i < 64 * 32; i += 256) {
        int nl = i >> 5, k4 = (i & 31) * 4;
        float4 v = *reinterpret_cast<const float4*>(&g_ik[(size_t)(n0 + nl) * ID_ + k4]);
        Bs[k4+0][nl] = v.x; Bs[k4+1][nl] = v.y; Bs[k4+2][nl] = v.z; Bs[k4+3][nl] = v.w;
    }

    float sacc[8][4];
    #pragma unroll
    for (int i = 0; i < 8; i++)
        #pragma unroll
        for (int j = 0; j < 4; j++) sacc[i][j] = 0.f;
    __syncthreads();

    const size_t lda = IH_ * ID_;
    for (int h = 0; h < IH_; h++) {
        const float* A = g_iq + (size_t)h * ID_ + (size_t)(m0 + a_m) * lda;
        {
            float4 v = *reinterpret_cast<const float4*>(&A[a_k]);
            As[0][a_k+0][a_m]=v.x; As[0][a_k+1][a_m]=v.y; As[0][a_k+2][a_m]=v.z; As[0][a_k+3][a_m]=v.w;
        }
        __syncthreads();
        u64 tacc[8][2];
        #pragma unroll
        for (int i = 0; i < 8; i++) { tacc[i][0] = 0ull; tacc[i][1] = 0ull; }
        int buf = 0;
        for (int k0 = 0; k0 < 128; k0 += 8) {
            float4 v;
            bool nxt = (k0 + 8) < 128;
            if (nxt) v = *reinterpret_cast<const float4*>(&A[k0 + 8 + a_k]);
            #pragma unroll
            for (int k = 0; k < 8; k++) {
                float4 a0 = *reinterpret_cast<const float4*>(&As[buf][k][ty * 8]);
                float4 a1 = *reinterpret_cast<const float4*>(&As[buf][k][ty * 8 + 4]);
                float4 b0 = *reinterpret_cast<const float4*>(&Bs[k0 + k][tx * 4]);
                u64 bb[2] = {pack2(b0.x,b0.y), pack2(b0.z,b0.w)};
                float ra[8] = {a0.x,a0.y,a0.z,a0.w,a1.x,a1.y,a1.z,a1.w};
                #pragma unroll
                for (int i = 0; i < 8; i++) {
                    u64 aa = pack2(ra[i], ra[i]);
                    ffma2(tacc[i][0], aa, bb[0]);
                    ffma2(tacc[i][1], aa, bb[1]);
                }
            }
            if (nxt) {
                int nb = buf ^ 1;
                As[nb][a_k+0][a_m]=v.x; As[nb][a_k+1][a_m]=v.y; As[nb][a_k+2][a_m]=v.z; As[nb][a_k+3][a_m]=v.w;
                __syncthreads();
                buf = nb;
            }
        }
        __syncthreads();
        #pragma unroll
        for (int i = 0; i < 8; i++) {
            float w = g_ckvx[(size_t)(m0 + ty * 8 + i) * CKVX_ + 576 + h];
            float2 t01 = unpack2(tacc[i][0]);
            float2 t23 = unpack2(tacc[i][1]);
            float tv[4] = {t01.x, t01.y, t23.x, t23.y};
            #pragma unroll
            for (int j = 0; j < 4; j++) {
                float add = __fmul_rn(w, fmaxf(tv[j], 0.f));
                sacc[i][j] = __fadd_rn(sacc[i][j], add);
            }
        }
    }
    #pragma unroll
    for (int i = 0; i < 8; i++) {
        int gm = m0 + ty * 8 + i;
        #pragma unroll
        for (int j = 0; j < 4; j++) {
            int gn = n0 + tx * 4 + j;
            g_scores[(size_t)gm * S_ + gn] = (gn <= gm) ? sacc[i][j] : NINF;
        }
    }
}

// ---------------- top-k (stable, jax tie semantics) ----------------
__device__ __forceinline__ unsigned fkey(float f) {
    unsigned u = __float_as_uint(f);
    return u ^ ((u >> 31) ? 0xFFFFFFFFu : 0x80000000u);
}

__global__ __launch_bounds__(256) void topk_kernel() {
    int q = blockIdx.x, t = threadIdx.x;
    const float* sc = g_scores + (size_t)q * S_;
    if (q < TOPK_) {
        for (int i = t; i <= q; i += 256) g_sel[(size_t)q * TOPK_ + i] = i;
        if (t == 0) g_nsel[q] = q + 1;
        return;
    }
    __shared__ unsigned hist[256];
    __shared__ unsigned s_pref, s_r;
    __shared__ int s_gt[257], s_eq[257];

    unsigned pref = 0, r = TOPK_;
    #pragma unroll
    for (int p = 3; p >= 0; p--) {
        hist[t] = 0;
        __syncthreads();
        for (int i = t; i < S_; i += 256) {
            unsigned u = fkey(sc[i]);
            bool ok = (p == 3) || ((u >> ((p + 1) * 8)) == pref);
            if (ok) atomicAdd(&hist[(u >> (p * 8)) & 255], 1u);
        }
        __syncthreads();
        if (t == 0) {
            unsigned run = 0;
            int b = 255;
            for (; b >= 0; b--) {
                unsigned c = hist[b];
                if (run + c >= r) break;
                run += c;
            }
            s_pref = (pref << 8) | (unsigned)b;
            s_r = r - run;
        }
        __syncthreads();
        pref = s_pref; r = s_r;
        __syncthreads();
    }
    unsigned T = pref;
    int need_eq = (int)r;

    int i0 = t * 8;
    unsigned keys[8];
    int cg = 0, ce = 0;
    #pragma unroll
    for (int k = 0; k < 8; k++) {
        unsigned u = fkey(sc[i0 + k]);
        keys[k] = u;
        cg += (u > T);
        ce += (u == T);
    }
    s_gt[t] = cg; s_eq[t] = ce;
    __syncthreads();
    if (t == 0) {
        int rg = 0, re = 0;
        for (int i = 0; i < 256; i++) {
            int a = s_gt[i]; s_gt[i] = rg; rg += a;
            int b2 = s_eq[i]; s_eq[i] = re; re += b2;
        }
        s_gt[256] = rg;
    }
    __syncthreads();
    int gpos = s_gt[t], epos = s_eq[t], total_gt = s_gt[256];
    int* out = g_sel + (size_t)q * TOPK_;
    #pragma unroll
    for (int k = 0; k < 8; k++) {
        unsigned u = keys[k];
        if (u > T) out[gpos++] = i0 + k;
        else if (u == T) {
            if (epos < need_eq) out[total_gt + epos] = i0 + k;
            epos++;
        }
    }
    if (t == 0) g_nsel[q] = TOPK_;
}

// ---------------- sparse attention (fp16 KV+kpe; fp32 math; fp16 attn out) --------
__global__ __launch_bounds__(128) void sparse_attn_kernel() {
    const float SCALE = 0.07216878364870322f;
    int qi = blockIdx.x, h = blockIdx.y;
    int t = threadIdx.x, w = t >> 5, lane = t & 31;
    __shared__ float qv[192];
    __shared__ float s_p[TOPK_];
    __shared__ int s_idx[TOPK_];
    __shared__ float s_red[4];
    __shared__ float s_out[4][128];

    int n = g_nsel[qi];
    const float* qptr = g_q + (size_t)qi * (H_ * 192) + h * 192;
    for (int i = t; i < 192; i += 128) qv[i] = qptr[i];
    for (int i = t; i < n; i += 128) s_idx[i] = g_sel[(size_t)qi * TOPK_ + i];
    __syncthreads();

    for (int j = w; j < n; j += 4) {
        int kidx = s_idx[j];
        const __half* kh = g_kvh + (size_t)kidx * (H_ * 256) + h * 256;
        uint2 raw = *reinterpret_cast<const uint2*>(kh + lane * 4);
        float2 f01 = __half22float2(*reinterpret_cast<const __half2*>(&raw.x));
        float2 f23 = __half22float2(*reinterpret_cast<const __half2*>(&raw.y));
        float4 a = reinterpret_cast<const float4*>(qv)[lane];
        float d = a.x * f01.x + a.y * f01.y + a.z * f23.x + a.w * f23.y;
        unsigned rawp = *reinterpret_cast<const unsigned*>(g_kpeh + (size_t)kidx * ROPE_ + lane * 2);
        float2 bp = __half22float2(*reinterpret_cast<const __half2*>(&rawp));
        float2 ap = reinterpret_cast<const float2*>(qv + 128)[lane];
        d += ap.x * bp.x + ap.y * bp.y;
        #pragma unroll
        for (int o = 16; o; o >>= 1) d += __shfl_down_sync(0xffffffffu, d, o);
        if (lane == 0) s_p[j] = d * SCALE;
    }
    __syncthreads();

    float m = -3.4e38f;
    for (int i = t; i < n; i += 128) m = fmaxf(m, s_p[i]);
    #pragma unroll
    for (int o = 16; o; o >>= 1) m = fmaxf(m, __shfl_xor_sync(0xffffffffu, m, o));
    if (lane == 0) s_red[w] = m;
    __syncthreads();
    m = fmaxf(fmaxf(s_red[0], s_red[1]), fmaxf(s_red[2], s_red[3]));
    __syncthreads();

    float sum = 0.f;
    for (int i = t; i < n; i += 128) {
        float e = __expf(s_p[i] - m);
        s_p[i] = e;
        sum += e;
    }
    #pragma unroll
    for (int o = 16; o; o >>= 1) sum += __shfl_xor_sync(0xffffffffu, sum, o);
    __syncthreads();
    if (lane == 0) s_red[w] = sum;
    __syncthreads();
    sum = s_red[0] + s_red[1] + s_red[2] + s_red[3];
    float inv = 1.0f / sum;

    float4 acc = make_float4(0.f, 0.f, 0.f, 0.f);
    for (int j = w; j < n; j += 4) {
        float p = s_p[j];
        int kidx = s_idx[j];
        const __half* vh = g_kvh + (size_t)kidx * (H_ * 256) + h * 256 + 128;
        uint2 raw = *reinterpret_cast<const uint2*>(vh + lane * 4);
        float2 v01 = __half22float2(*reinterpret_cast<const __half2*>(&raw.x));
        float2 v23 = __half22float2(*reinterpret_cast<const __half2*>(&raw.y));
        acc.x += p * v01.x; acc.y += p * v01.y; acc.z += p * v23.x; acc.w += p * v23.y;
    }
    reinterpret_cast<float4*>(&s_out[w][0])[lane] = acc;
    __syncthreads();
    float o = (s_out[0][t] + s_out[1][t] + s_out[2][t] + s_out[3][t]) * inv;
    g_attnh[(size_t)qi * (H_ * VDIM_) + h * VDIM_ + t] = __float2half_rn(o);
}

// ---------------- launch ----------------
extern "C" void kernel_launch(void* const* d_in, const int* in_sizes, int n_in,
                              void* d_out, int out_size) {
    (void)in_sizes; (void)n_in; (void)out_size;
    const float* hidden      = (const float*)d_in[0];
    const float* q_a_w       = (const float*)d_in[1];
    const float* q_a_ln_w    = (const float*)d_in[2];
    const float* q_b_w       = (const float*)d_in[3];
    const float* kv_a_w      = (const float*)d_in[4];
    const float* kv_a_ln_w   = (const float*)d_in[5];
    const float* kv_b_w      = (const float*)d_in[6];
    const float* o_w         = (const float*)d_in[7];
    const float* idx_wq_b_w  = (const float*)d_in[8];
    const float* idx_wk_w    = (const float*)d_in[9];
    const float* idx_kn_w    = (const float*)d_in[10];
    const float* idx_kn_b    = (const float*)d_in[11];
    const float* idx_wproj_w = (const float*)d_in[12];
    float* out = (float*)d_out;

    float  *p_qr, *p_q, *p_iq, *p_ikpre;
    __half *p_qrh, *p_ckvnh, *p_kvh, *p_attnh, *p_qbwh, *p_kvbwh, *p_owh;
    cudaGetSymbolAddress((void**)&p_qr,    g_qr);
    cudaGetSymbolAddress((void**)&p_q,     g_q);
    cudaGetSymbolAddress((void**)&p_iq,    g_iq);
    cudaGetSymbolAddress((void**)&p_ikpre, g_ikpre);
    cudaGetSymbolAddress((void**)&p_qrh,   g_qrh);
    cudaGetSymbolAddress((void**)&p_ckvnh, g_ckvnh);
    cudaGetSymbolAddress((void**)&p_kvh,   g_kvh);
    cudaGetSymbolAddress((void**)&p_attnh, g_attnh);
    cudaGetSymbolAddress((void**)&p_qbwh,  g_qbwh);
    cudaGetSymbolAddress((void**)&p_kvbwh, g_kvbwh);
    cudaGetSymbolAddress((void**)&p_owh,   g_owh);

    dim3 tb(256);

    cossin_kernel<<<S_, 32>>>();
    build_bext_kernel<<<(CKVX_ * HID_ / 4 + 255) / 256, 256>>>(kv_a_w, idx_wproj_w);
    f2h_kernel<<<((H_*192)*QR_/4 + 255)/256, 256>>>(q_b_w,  p_qbwh,  (H_*192)*QR_/4);
    f2h_kernel<<<((H_*256)*KVR_/4 + 255)/256, 256>>>(kv_b_w, p_kvbwh, (H_*256)*KVR_/4);
    f2h_kernel<<<(HID_*(H_*VDIM_)/4 + 255)/256, 256>>>(o_w,  p_owh,   HID_*(H_*VDIM_)/4);

    // qr | ckvx(incl 0.25*iw) | ik — 288 blocks, single wave over A=hidden (K=2048)
    fused_hidden_gemm<<<dim3(18, S_ / 128), tb>>>(hidden, q_a_w, idx_wk_w);
    rmsnorm_kernel<<<S_, 256>>>(p_qr, p_qrh, q_a_ln_w, QR_);
    ckv_split_kernel<<<S_, 256>>>(kv_a_ln_w);
    ik_ln_rope_kernel<<<S_, 128>>>(p_ikpre, idx_kn_w, idx_kn_b);

    // iq (fp32, top-k critical; same body/k-order -> bit-identical)
    sgemm_nt_db<<<dim3((IH_*ID_)/128, S_/128), tb>>>(p_qr, QR_, idx_wq_b_w, QR_, p_iq, IH_*ID_, S_, IH_*ID_, QR_, 1.f);

    // q and kv via fp16 tensor cores (smooth path)
    hgemm_nt<<<dim3((H_*192)/128, S_/128), tb>>>(p_qrh, QR_, p_qbwh, QR_, p_q, H_*192, QR_, 0);
    hgemm_nt<<<dim3((H_*256)/128, S_/128), tb>>>(p_ckvnh, KVR_, p_kvbwh, KVR_, p_kvh, H_*256, KVR_, 1);

    // rope q_pe and iq
    rope_kernel<<<S_, dim3(32, H_)>>>(p_q + NOPE_, H_ * 192, 192);
    rope_kernel<<<S_, dim3(32, IH_)>>>(p_iq, IH_ * ID_, ID_);

    // fused indexer scores (causal skip + FFMA2)
    idx_scores_kernel<<<dim3(S_ / 64, S_ / 128), tb>>>();

    topk_kernel<<<S_, 256>>>();

    sparse_attn_kernel<<<dim3(S_, H_), 128>>>();

    // out = attn @ o_w^T via fp16 tensor cores
    hgemm_nt<<<dim3(HID_/128, S_/128), tb>>>(p_attnh, H_*VDIM_, p_owh, H_*VDIM_, out, HID_, H_*VDIM_, 0);
}

// round 16
// speedup vs baseline: 1.4942x; 1.0481x over previous
#include <cuda_runtime.h>
#include <cuda_fp16.h>
#include <math.h>

#define S_    2048
#define HID_  2048
#define H_    16
#define NOPE_ 128
#define ROPE_ 64
#define VDIM_ 128
#define QR_   1536
#define KVR_  512
#define IH_   16
#define ID_   128
#define TOPK_ 512
#define EPS_  1e-6f
#define CKVX_ 640

typedef unsigned long long u64;

__device__ __forceinline__ void ffma2(u64 &d, u64 a, u64 b) {
    asm("fma.rn.f32x2 %0, %1, %2, %0;" : "+l"(d) : "l"(a), "l"(b));
}
__device__ __forceinline__ u64 pack2(float lo, float hi) {
    u64 r; asm("mov.b64 %0, {%1, %2};" : "=l"(r) : "f"(lo), "f"(hi)); return r;
}
__device__ __forceinline__ float2 unpack2(u64 v) {
    float2 r; asm("mov.b64 {%0, %1}, %2;" : "=f"(r.x), "=f"(r.y) : "l"(v)); return r;
}
__device__ __forceinline__ unsigned sptr(const void* p) {
    return (unsigned)__cvta_generic_to_shared(p);
}

// ---------------- scratch ----------------
__device__ float  g_qr    [S_*QR_];
__device__ __half g_qrh   [S_*QR_];
__device__ float  g_q     [S_*H_*(NOPE_+ROPE_)];
__device__ float  g_ckvx  [S_*CKVX_];
__device__ float  g_bext  [CKVX_*HID_];
__device__ __half g_ckvnh [S_*KVR_];
__device__ __half g_kpeh  [S_*ROPE_];
__device__ __half g_kvh   [S_*H_*(NOPE_+VDIM_)];
__device__ float  g_iq    [S_*IH_*ID_];
__device__ float  g_ikpre [S_*ID_];
__device__ float  g_ik    [S_*ID_];
__device__ float  g_scores[S_*S_];
__device__ int    g_sel   [S_*TOPK_];
__device__ int    g_nsel  [S_];
__device__ __half g_attnh [S_*H_*VDIM_];
__device__ __half g_qbwh  [(H_*192)*QR_];
__device__ __half g_kvbwh [(H_*256)*KVR_];
__device__ __half g_owh   [HID_*(H_*VDIM_)];
__device__ float  g_cosb  [S_*32];
__device__ float  g_sinb  [S_*32];

// ---------------- helpers ----------------
__device__ __forceinline__ float blockReduceSum(float v, float* sh) {
    int lane = threadIdx.x & 31, w = threadIdx.x >> 5;
    #pragma unroll
    for (int o = 16; o; o >>= 1) v += __shfl_xor_sync(0xffffffffu, v, o);
    if (lane == 0) sh[w] = v;
    __syncthreads();
    int nw = (blockDim.x + 31) >> 5;
    float r = (threadIdx.x < nw) ? sh[threadIdx.x] : 0.f;
    if (w == 0) {
        #pragma unroll
        for (int o = 16; o; o >>= 1) r += __shfl_xor_sync(0xffffffffu, r, o);
        if (lane == 0) sh[0] = r;
    }
    __syncthreads();
    float out = sh[0];
    __syncthreads();
    return out;
}

__global__ void cossin_kernel() {
    int s = blockIdx.x, d = threadIdx.x;
    float e = (float)(2 * d) / 64.0f;
    float pf = (float)pow(10000.0, (double)e);
    float inv = __fdiv_rn(1.0f, pf);
    float f = __fmul_rn((float)s, inv);
    g_cosb[s * 32 + d] = (float)cos((double)f);
    g_sinb[s * 32 + d] = (float)sin((double)f);
}

__global__ __launch_bounds__(256) void f2h_kernel(const float* __restrict__ src,
                                                  __half* __restrict__ dst, int n4) {
    int i = blockIdx.x * 256 + threadIdx.x;
    if (i < n4) {
        float4 v = reinterpret_cast<const float4*>(src)[i];
        reinterpret_cast<__half2*>(dst)[i * 2]     = __floats2half2_rn(v.x, v.y);
        reinterpret_cast<__half2*>(dst)[i * 2 + 1] = __floats2half2_rn(v.z, v.w);
    }
}

__global__ __launch_bounds__(256) void build_bext_kernel(
    const float* __restrict__ kv_a_w, const float* __restrict__ idx_wproj_w)
{
    size_t idx = (size_t)blockIdx.x * 256 + threadIdx.x;
    size_t row = idx / (HID_ / 4), c4 = idx % (HID_ / 4);
    float4 v;
    if (row < 576) {
        v = reinterpret_cast<const float4*>(kv_a_w)[row * (HID_ / 4) + c4];
    } else if (row < 592) {
        v = reinterpret_cast<const float4*>(idx_wproj_w)[(row - 576) * (HID_ / 4) + c4];
        v.x *= 0.25f; v.y *= 0.25f; v.z *= 0.25f; v.w *= 0.25f;
    } else {
        v = make_float4(0.f, 0.f, 0.f, 0.f);
    }
    reinterpret_cast<float4*>(g_bext)[idx] = v;
}

// ============ fp32 GEMM body (indexer-critical path): 128x128, quadrant, FFMA2 ============
__device__ __forceinline__ void gemm_body_128(
    const float* __restrict__ A, int lda,
    const float* __restrict__ B, int ldb,
    float* __restrict__ C, int ldc,
    int M, int N, int K, float alpha,
    int m0, int n0,
    float (*As)[8][128], float (*Bs)[8][128])
{
    int t = threadIdx.x;
    int tx = t & 15, ty = t >> 4;
    int a_m = t >> 1, a_k = (t & 1) * 4;
    int gmA = m0 + a_m, gnB = n0 + a_m;
    u64 acc[8][4];
    #pragma unroll
    for (int i = 0; i < 8; i++)
        #pragma unroll
        for (int j = 0; j < 4; j++) acc[i][j] = 0ull;

    float4 va = make_float4(0.f,0.f,0.f,0.f), vb = va;
    if (gmA < M) va = *reinterpret_cast<const float4*>(&A[(size_t)gmA * lda + a_k]);
    if (gnB < N) vb = *reinterpret_cast<const float4*>(&B[(size_t)gnB * ldb + a_k]);
    As[0][a_k+0][a_m]=va.x; As[0][a_k+1][a_m]=va.y; As[0][a_k+2][a_m]=va.z; As[0][a_k+3][a_m]=va.w;
    Bs[0][a_k+0][a_m]=vb.x; Bs[0][a_k+1][a_m]=vb.y; Bs[0][a_k+2][a_m]=vb.z; Bs[0][a_k+3][a_m]=vb.w;
    __syncthreads();
    int buf = 0;
    for (int k0 = 0; k0 < K; k0 += 8) {
        bool nxt = (k0 + 8) < K;
        if (nxt) {
            va = make_float4(0.f,0.f,0.f,0.f); vb = va;
            if (gmA < M) va = *reinterpret_cast<const float4*>(&A[(size_t)gmA * lda + k0 + 8 + a_k]);
            if (gnB < N) vb = *reinterpret_cast<const float4*>(&B[(size_t)gnB * ldb + k0 + 8 + a_k]);
        }
        #pragma unroll
        for (int k = 0; k < 8; k++) {
            float4 a0 = *reinterpret_cast<const float4*>(&As[buf][k][ty * 4]);
            float4 a1 = *reinterpret_cast<const float4*>(&As[buf][k][64 + ty * 4]);
            float4 b0 = *reinterpret_cast<const float4*>(&Bs[buf][k][tx * 4]);
            float4 b1 = *reinterpret_cast<const float4*>(&Bs[buf][k][64 + tx * 4]);
            u64 bb[4] = {pack2(b0.x,b0.y), pack2(b0.z,b0.w), pack2(b1.x,b1.y), pack2(b1.z,b1.w)};
            float ra[8] = {a0.x,a0.y,a0.z,a0.w,a1.x,a1.y,a1.z,a1.w};
            #pragma unroll
            for (int i = 0; i < 8; i++) {
                u64 aa = pack2(ra[i], ra[i]);
                #pragma unroll
                for (int j = 0; j < 4; j++) ffma2(acc[i][j], aa, bb[j]);
            }
        }
        if (nxt) {
            int nb = buf ^ 1;
            As[nb][a_k+0][a_m]=va.x; As[nb][a_k+1][a_m]=va.y; As[nb][a_k+2][a_m]=va.z; As[nb][a_k+3][a_m]=va.w;
            Bs[nb][a_k+0][a_m]=vb.x; Bs[nb][a_k+1][a_m]=vb.y; Bs[nb][a_k+2][a_m]=vb.z; Bs[nb][a_k+3][a_m]=vb.w;
            __syncthreads();
            buf = nb;
        }
    }
    #pragma unroll
    for (int i = 0; i < 8; i++) {
        int gm = m0 + ((i < 4) ? (ty * 4 + i) : (64 + ty * 4 + i - 4));
        if (gm >= M) continue;
        #pragma unroll
        for (int j = 0; j < 4; j++) {
            float2 v = unpack2(acc[i][j]);
            int gn = n0 + ((j < 2) ? (tx * 4 + j * 2) : (64 + tx * 4 + (j - 2) * 2));
            if (gn < N)     C[(size_t)gm * ldc + gn]     = alpha * v.x;
            if (gn + 1 < N) C[(size_t)gm * ldc + gn + 1] = alpha * v.y;
        }
    }
}

__global__ __launch_bounds__(256, 2) void sgemm_nt_db(
    const float* __restrict__ A, int lda,
    const float* __restrict__ B, int ldb,
    float* __restrict__ C, int ldc,
    int M, int N, int K, float alpha)
{
    __shared__ float As[2][8][128];
    __shared__ float Bs[2][8][128];
    gemm_body_128(A, lda, B, ldb, C, ldc, M, N, K, alpha,
                  blockIdx.y * 128, blockIdx.x * 128, As, Bs);
}

// ---------------- fused A=hidden (K=2048): qr | ckvx(incl iw) | ik — 288 blocks ----------------
__global__ __launch_bounds__(256, 2) void fused_hidden_gemm(
    const float* __restrict__ A,
    const float* __restrict__ Bqr, const float* __restrict__ Bik)
{
    __shared__ float As[2][8][128];
    __shared__ float Bs[2][8][128];
    int bx = blockIdx.x;
    const float* B; float* C; int N, ldc, n0;
    if (bx < 12)      { B = Bqr;    C = g_qr;    N = QR_;   ldc = QR_;   n0 = bx * 128; }
    else if (bx < 17) { B = g_bext; C = g_ckvx;  N = CKVX_; ldc = CKVX_; n0 = (bx - 12) * 128; }
    else              { B = Bik;    C = g_ikpre; N = ID_;   ldc = ID_;   n0 = 0; }
    gemm_body_128(A, HID_, B, HID_, C, ldc, S_, N, HID_, 1.f,
                  blockIdx.y * 128, n0, As, Bs);
}

// ============ fp16 tensor-core GEMM body (fp32 accumulate) ============
#define AS_H(b,r,c) Ash[(b)*3072 + (r)*24 + (c)]
#define BS_H(b,r,c) Bsh[(b)*3072 + (r)*24 + (c)]
__device__ __forceinline__ void hgemm_body(
    const __half* __restrict__ A, int lda,
    const __half* __restrict__ B, int ldb,
    void* __restrict__ Cv, int ldc,
    int K, int halfOut, int m0, int n0,
    __half* Ash, __half* Bsh)
{
    int t = threadIdx.x;
    int lane = t & 31, wid = t >> 5;
    int wm = (wid & 1) * 64, wn = (wid >> 1) * 32;
    int l_r = t >> 1, l_c = (t & 1) * 8;

    float acc[4][4][4];
    #pragma unroll
    for (int i = 0; i < 4; i++)
        #pragma unroll
        for (int j = 0; j < 4; j++)
            #pragma unroll
            for (int c = 0; c < 4; c++) acc[i][j][c] = 0.f;

    uint4 va = *reinterpret_cast<const uint4*>(&A[(size_t)(m0 + l_r) * lda + l_c]);
    uint4 vb = *reinterpret_cast<const uint4*>(&B[(size_t)(n0 + l_r) * ldb + l_c]);
    *reinterpret_cast<uint4*>(&AS_H(0, l_r, l_c)) = va;
    *reinterpret_cast<uint4*>(&BS_H(0, l_r, l_c)) = vb;
    __syncthreads();

    int a_row = lane & 15, a_col = (lane >> 4) * 8;
    int b_row = lane & 7,  b_col = ((lane >> 3) & 1) * 8;

    int buf = 0;
    for (int k0 = 0; k0 < K; k0 += 16) {
        bool nxt = (k0 + 16) < K;
        if (nxt) {
            va = *reinterpret_cast<const uint4*>(&A[(size_t)(m0 + l_r) * lda + k0 + 16 + l_c]);
            vb = *reinterpret_cast<const uint4*>(&B[(size_t)(n0 + l_r) * ldb + k0 + 16 + l_c]);
        }
        unsigned af[4][4], bf[4][2];
        #pragma unroll
        for (int i = 0; i < 4; i++) {
            unsigned addr = sptr(&AS_H(buf, wm + 16 * i + a_row, a_col));
            asm volatile("ldmatrix.sync.aligned.m8n8.x4.shared.b16 {%0,%1,%2,%3}, [%4];"
                : "=r"(af[i][0]), "=r"(af[i][1]), "=r"(af[i][2]), "=r"(af[i][3]) : "r"(addr));
        }
        #pragma unroll
        for (int j = 0; j < 4; j++) {
            unsigned addr = sptr(&BS_H(buf, wn + 8 * j + b_row, b_col));
            asm volatile("ldmatrix.sync.aligned.m8n8.x2.shared.b16 {%0,%1}, [%2];"
                : "=r"(bf[j][0]), "=r"(bf[j][1]) : "r"(addr));
        }
        #pragma unroll
        for (int i = 0; i < 4; i++)
            #pragma unroll
            for (int j = 0; j < 4; j++)
                asm volatile("mma.sync.aligned.m16n8k16.row.col.f32.f16.f16.f32 "
                    "{%0,%1,%2,%3}, {%4,%5,%6,%7}, {%8,%9}, {%0,%1,%2,%3};"
                    : "+f"(acc[i][j][0]), "+f"(acc[i][j][1]), "+f"(acc[i][j][2]), "+f"(acc[i][j][3])
                    : "r"(af[i][0]), "r"(af[i][1]), "r"(af[i][2]), "r"(af[i][3]),
                      "r"(bf[j][0]), "r"(bf[j][1]));
        if (nxt) {
            int nb = buf ^ 1;
            *reinterpret_cast<uint4*>(&AS_H(nb, l_r, l_c)) = va;
            *reinterpret_cast<uint4*>(&BS_H(nb, l_r, l_c)) = vb;
            __syncthreads();
            buf = nb;
        }
    }

    int r = lane >> 2, cpair = (lane & 3) * 2;
    #pragma unroll
    for (int i = 0; i < 4; i++) {
        int gm0 = m0 + wm + 16 * i + r;
        #pragma unroll
        for (int j = 0; j < 4; j++) {
            int gn = n0 + wn + 8 * j + cpair;
            if (halfOut) {
                __half* C = reinterpret_cast<__half*>(Cv);
                *reinterpret_cast<__half2*>(&C[(size_t)gm0 * ldc + gn]) =
                    __floats2half2_rn(acc[i][j][0], acc[i][j][1]);
                *reinterpret_cast<__half2*>(&C[(size_t)(gm0 + 8) * ldc + gn]) =
                    __floats2half2_rn(acc[i][j][2], acc[i][j][3]);
            } else {
                float* C = reinterpret_cast<float*>(Cv);
                C[(size_t)gm0 * ldc + gn]           = acc[i][j][0];
                C[(size_t)gm0 * ldc + gn + 1]       = acc[i][j][1];
                C[(size_t)(gm0 + 8) * ldc + gn]     = acc[i][j][2];
                C[(size_t)(gm0 + 8) * ldc + gn + 1] = acc[i][j][3];
            }
        }
    }
}

// ---------------- standalone hgemm (o_w) ----------------
__global__ __launch_bounds__(256, 2) void hgemm_nt(
    const __half* __restrict__ A, int lda,
    const __half* __restrict__ B, int ldb,
    void* __restrict__ Cv, int ldc,
    int K, int halfOut)
{
    __shared__ __half smemh[2 * 3072 * 2];
    hgemm_body(A, lda, B, ldb, Cv, ldc, K, halfOut,
               blockIdx.y * 128, blockIdx.x * 128, smemh, smemh + 2 * 3072);
}

// ============ merged mid-stage: iq (fp32, fma) | q hgemm | kv hgemm (tensor) ============
// 1D grid of 1152 blocks: [0,256) iq (16n x 16m), [256,640) q (24n x 16m),
// [640,1152) kv (32n x 16m). iq blocks first so the long fp32 blocks start in wave 1.
__global__ __launch_bounds__(256, 2) void fused_mid_gemm(
    const float* __restrict__ Biq)
{
    __shared__ char smem[24576];
    int bx = blockIdx.x;
    if (bx < 256) {
        float (*As)[8][128] = reinterpret_cast<float (*)[8][128]>(smem);
        float (*Bs)[8][128] = reinterpret_cast<float (*)[8][128]>(smem + 8192);
        int n0 = (bx & 15) * 128, m0 = (bx >> 4) * 128;
        gemm_body_128(g_qr, QR_, Biq, QR_, g_iq, IH_ * ID_, S_, IH_ * ID_, QR_, 1.f,
                      m0, n0, As, Bs);
    } else if (bx < 640) {
        __half* Ash = reinterpret_cast<__half*>(smem);
        __half* Bsh = Ash + 2 * 3072;
        int idx = bx - 256;
        int n0 = (idx % 24) * 128, m0 = (idx / 24) * 128;
        hgemm_body(g_qrh, QR_, g_qbwh, QR_, g_q, H_ * 192, QR_, 0, m0, n0, Ash, Bsh);
    } else {
        __half* Ash = reinterpret_cast<__half*>(smem);
        __half* Bsh = Ash + 2 * 3072;
        int idx = bx - 640;                       // 512 blocks: 32 n-tiles x 16 m-tiles
        int n0 = (idx & 31) * 128, m0 = (idx >> 5) * 128;
        hgemm_body(g_ckvnh, KVR_, g_kvbwh, KVR_, g_kvh, H_ * 256, KVR_, 1, m0, n0, Ash, Bsh);
    }
}

// ---------------- rmsnorm (in-place fp32 + fp16 copy) ----------------
__global__ __launch_bounds__(256) void rmsnorm_kernel(float* __restrict__ x,
                                                      __half* __restrict__ xh,
                                                      const float* __restrict__ w, int n) {
    __shared__ float sh[33];
    int row = blockIdx.x, t = threadIdx.x;
    float* p = x + (size_t)row * n;
    int cnt = n / 256;
    float local[8];
    float ss = 0.f;
    for (int i = 0; i < cnt; i++) { float v = p[t + i * 256]; local[i] = v; ss += v * v; }
    float total = blockReduceSum(ss, sh);
    float scale = rsqrtf(total / (float)n + EPS_);
    for (int i = 0; i < cnt; i++) {
        float o = local[i] * scale * w[t + i * 256];
        p[t + i * 256] = o;
        xh[(size_t)row * n + t + i * 256] = __float2half_rn(o);
    }
}

// ---------------- ckv split (ckvn fp16; kpe fp16) ----------------
__global__ __launch_bounds__(256) void ckv_split_kernel(const float* __restrict__ w) {
    __shared__ float sh[33];
    int s = blockIdx.x, t = threadIdx.x;
    const float* p = g_ckvx + (size_t)s * CKVX_;
    float v0 = p[t], v1 = p[256 + t];
    float total = blockReduceSum(v0 * v0 + v1 * v1, sh);
    float scale = rsqrtf(total / (float)KVR_ + EPS_);
    g_ckvnh[(size_t)s * KVR_ + t]       = __float2half_rn(v0 * scale * w[t]);
    g_ckvnh[(size_t)s * KVR_ + 256 + t] = __float2half_rn(v1 * scale * w[256 + t]);
    if (t < 32) {
        float x1 = p[KVR_ + t], x2 = p[KVR_ + 32 + t];
        float c = g_cosb[s * 32 + t], sn = g_sinb[s * 32 + t];
        g_kpeh[s * ROPE_ + t]      = __float2half_rn(x1 * c - x2 * sn);
        g_kpeh[s * ROPE_ + 32 + t] = __float2half_rn(x2 * c + x1 * sn);
    }
}

// ---------------- layernorm + rope for ik ----------------
__global__ __launch_bounds__(128) void ik_ln_rope_kernel(const float* __restrict__ xin,
                                                         const float* __restrict__ w,
                                                         const float* __restrict__ b) {
    __shared__ float sh[33];
    __shared__ float sn_[128];
    int s = blockIdx.x, t = threadIdx.x;
    float x = xin[(size_t)s * ID_ + t];
    float mean = blockReduceSum(x, sh) / (float)ID_;
    float var = blockReduceSum(x * x, sh) / (float)ID_ - mean * mean;
    float nv = (x - mean) * rsqrtf(var + EPS_) * w[t] + b[t];
    sn_[t] = nv;
    __syncthreads();
    float out;
    if (t < 32) {
        float c = g_cosb[s * 32 + t], snv = g_sinb[s * 32 + t];
        out = sn_[t] * c - sn_[t + 32] * snv;
    } else if (t < 64) {
        float c = g_cosb[s * 32 + (t - 32)], snv = g_sinb[s * 32 + (t - 32)];
        out = sn_[t] * c + sn_[t - 32] * snv;
    } else {
        out = nv;
    }
    g_ik[(size_t)s * ID_ + t] = out;
}

// ---------------- generic in-place rope over heads ----------------
__global__ void rope_kernel(float* __restrict__ base, int rowStride, int headStride) {
    int s = blockIdx.x;
    int h = threadIdx.y, d = threadIdx.x;
    float* p = base + (size_t)s * rowStride + h * headStride;
    float c = g_cosb[s * 32 + d], sn = g_sinb[s * 32 + d];
    float x1 = p[d], x2 = p[d + 32];
    p[d] = x1 * c - x2 * sn;
    p[d + 32] = x2 * c + x1 * sn;
}

// ============ fused indexer w/ FFMA2 + causal skip ============
__global__ __launch_bounds__(256, 2) void idx_scores_kernel() {
    int m0 = blockIdx.y * 128, n0 = blockIdx.x * 64;
    int t = threadIdx.x;
    int tx = t & 15, ty = t >> 4;
    const float NINF = __int_as_float(0xff800000);

    if (m0 + 128 <= TOPK_) return;
    if (n0 >= m0 + 128) {
        #pragma unroll
        for (int i = 0; i < 8; i++) {
            int gm = m0 + ty * 8 + i;
            #pragma unroll
            for (int j = 0; j < 4; j++)
                g_scores[(size_t)gm * S_ + n0 + tx * 4 + j] = NINF;
        }
        return;
    }

    __shared__ float Bs[128][64];
    __shared__ float As[2][8][128];
    int a_m = t >> 1, a_k = (t & 1) * 4;

    for (int i = t; i < 64 * 32; i += 256) {
        int nl = i >> 5, k4 = (i & 31) * 4;
        float4 v = *reinterpret_cast<const float4*>(&g_ik[(size_t)(n0 + nl) * ID_ + k4]);
        Bs[k4+0][nl] = v.x; Bs[k4+1][nl] = v.y; Bs[k4+2][nl] = v.z; Bs[k4+3][nl] = v.w;
    }

    float sacc[8][4];
    #pragma unroll
    for (int i = 0; i < 8; i++)
        #pragma unroll
        for (int j = 0; j < 4; j++) sacc[i][j] = 0.f;
    __syncthreads();

    const size_t lda = IH_ * ID_;
    for (int h = 0; h < IH_; h++) {
        const float* A = g_iq + (size_t)h * ID_ + (size_t)(m0 + a_m) * lda;
        {
            float4 v = *reinterpret_cast<const float4*>(&A[a_k]);
            As[0][a_k+0][a_m]=v.x; As[0][a_k+1][a_m]=v.y; As[0][a_k+2][a_m]=v.z; As[0][a_k+3][a_m]=v.w;
        }
        __syncthreads();
        u64 tacc[8][2];
        #pragma unroll
        for (int i = 0; i < 8; i++) { tacc[i][0] = 0ull; tacc[i][1] = 0ull; }
        int buf = 0;
        for (int k0 = 0; k0 < 128; k0 += 8) {
            float4 v;
            bool nxt = (k0 + 8) < 128;
            if (nxt) v = *reinterpret_cast<const float4*>(&A[k0 + 8 + a_k]);
            #pragma unroll
            for (int k = 0; k < 8; k++) {
                float4 a0 = *reinterpret_cast<const float4*>(&As[buf][k][ty * 8]);
                float4 a1 = *reinterpret_cast<const float4*>(&As[buf][k][ty * 8 + 4]);
                float4 b0 = *reinterpret_cast<const float4*>(&Bs[k0 + k][tx * 4]);
                u64 bb[2] = {pack2(b0.x,b0.y), pack2(b0.z,b0.w)};
                float ra[8] = {a0.x,a0.y,a0.z,a0.w,a1.x,a1.y,a1.z,a1.w};
                #pragma unroll
                for (int i = 0; i < 8; i++) {
                    u64 aa = pack2(ra[i], ra[i]);
                    ffma2(tacc[i][0], aa, bb[0]);
                    ffma2(tacc[i][1], aa, bb[1]);
                }
            }
            if (nxt) {
                int nb = buf ^ 1;
                As[nb][a_k+0][a_m]=v.x; As[nb][a_k+1][a_m]=v.y; As[nb][a_k+2][a_m]=v.z; As[nb][a_k+3][a_m]=v.w;
                __syncthreads();
                buf = nb;
            }
        }
        __syncthreads();
        #pragma unroll
        for (int i = 0; i < 8; i++) {
            float w = g_ckvx[(size_t)(m0 + ty * 8 + i) * CKVX_ + 576 + h];
            float2 t01 = unpack2(tacc[i][0]);
            float2 t23 = unpack2(tacc[i][1]);
            float tv[4] = {t01.x, t01.y, t23.x, t23.y};
            #pragma unroll
            for (int j = 0; j < 4; j++) {
                float add = __fmul_rn(w, fmaxf(tv[j], 0.f));
                sacc[i][j] = __fadd_rn(sacc[i][j], add);
            }
        }
    }
    #pragma unroll
    for (int i = 0; i < 8; i++) {
        int gm = m0 + ty * 8 + i;
        #pragma unroll
        for (int j = 0; j < 4; j++) {
            int gn = n0 + tx * 4 + j;
            g_scores[(size_t)gm * S_ + gn] = (gn <= gm) ? sacc[i][j] : NINF;
        }
    }
}

// ---------------- top-k (stable, jax tie semantics) ----------------
__device__ __forceinline__ unsigned fkey(float f) {
    unsigned u = __float_as_uint(f);
    return u ^ ((u >> 31) ? 0xFFFFFFFFu : 0x80000000u);
}

__global__ __launch_bounds__(256) void topk_kernel() {
    int q = blockIdx.x, t = threadIdx.x;
    const float* sc = g_scores + (size_t)q * S_;
    if (q < TOPK_) {
        for (int i = t; i <= q; i += 256) g_sel[(size_t)q * TOPK_ + i] = i;
        if (t == 0) g_nsel[q] = q + 1;
        return;
    }
    __shared__ unsigned hist[256];
    __shared__ unsigned s_pref, s_r;
    __shared__ int s_gt[257], s_eq[257];

    unsigned pref = 0, r = TOPK_;
    #pragma unroll
    for (int p = 3; p >= 0; p--) {
        hist[t] = 0;
        __syncthreads();
        for (int i = t; i < S_; i += 256) {
            unsigned u = fkey(sc[i]);
            bool ok = (p == 3) || ((u >> ((p + 1) * 8)) == pref);
            if (ok) atomicAdd(&hist[(u >> (p * 8)) & 255], 1u);
        }
        __syncthreads();
        if (t == 0) {
            unsigned run = 0;
            int b = 255;
            for (; b >= 0; b--) {
                unsigned c = hist[b];
                if (run + c >= r) break;
                run += c;
            }
            s_pref = (pref << 8) | (unsigned)b;
            s_r = r - run;
        }
        __syncthreads();
        pref = s_pref; r = s_r;
        __syncthreads();
    }
    unsigned T = pref;
    int need_eq = (int)r;

    int i0 = t * 8;
    unsigned keys[8];
    int cg = 0, ce = 0;
    #pragma unroll
    for (int k = 0; k < 8; k++) {
        unsigned u = fkey(sc[i0 + k]);
        keys[k] = u;
        cg += (u > T);
        ce += (u == T);
    }
    s_gt[t] = cg; s_eq[t] = ce;
    __syncthreads();
    if (t == 0) {
        int rg = 0, re = 0;
        for (int i = 0; i < 256; i++) {
            int a = s_gt[i]; s_gt[i] = rg; rg += a;
            int b2 = s_eq[i]; s_eq[i] = re; re += b2;
        }
        s_gt[256] = rg;
    }
    __syncthreads();
    int gpos = s_gt[t], epos = s_eq[t], total_gt = s_gt[256];
    int* out = g_sel + (size_t)q * TOPK_;
    #pragma unroll
    for (int k = 0; k < 8; k++) {
        unsigned u = keys[k];
        if (u > T) out[gpos++] = i0 + k;
        else if (u == T) {
            if (epos < need_eq) out[total_gt + epos] = i0 + k;
            epos++;
        }
    }
    if (t == 0) g_nsel[q] = TOPK_;
}

// ---------------- sparse attention (fp16 KV+kpe; fp32 math; fp16 attn out) --------
__global__ __launch_bounds__(128) void sparse_attn_kernel() {
    const float SCALE = 0.07216878364870322f;
    int qi = blockIdx.x, h = blockIdx.y;
    int t = threadIdx.x, w = t >> 5, lane = t & 31;
    __shared__ float qv[192];
    __shared__ float s_p[TOPK_];
    __shared__ int s_idx[TOPK_];
    __shared__ float s_red[4];
    __shared__ float s_out[4][128];

    int n = g_nsel[qi];
    const float* qptr = g_q + (size_t)qi * (H_ * 192) + h * 192;
    for (int i = t; i < 192; i += 128) qv[i] = qptr[i];
    for (int i = t; i < n; i += 128) s_idx[i] = g_sel[(size_t)qi * TOPK_ + i];
    __syncthreads();

    for (int j = w; j < n; j += 4) {
        int kidx = s_idx[j];
        const __half* kh = g_kvh + (size_t)kidx * (H_ * 256) + h * 256;
        uint2 raw = *reinterpret_cast<const uint2*>(kh + lane * 4);
        float2 f01 = __half22float2(*reinterpret_cast<const __half2*>(&raw.x));
        float2 f23 = __half22float2(*reinterpret_cast<const __half2*>(&raw.y));
        float4 a = reinterpret_cast<const float4*>(qv)[lane];
        float d = a.x * f01.x + a.y * f01.y + a.z * f23.x + a.w * f23.y;
        unsigned rawp = *reinterpret_cast<const unsigned*>(g_kpeh + (size_t)kidx * ROPE_ + lane * 2);
        float2 bp = __half22float2(*reinterpret_cast<const __half2*>(&rawp));
        float2 ap = reinterpret_cast<const float2*>(qv + 128)[lane];
        d += ap.x * bp.x + ap.y * bp.y;
        #pragma unroll
        for (int o = 16; o; o >>= 1) d += __shfl_down_sync(0xffffffffu, d, o);
        if (lane == 0) s_p[j] = d * SCALE;
    }
    __syncthreads();

    float m = -3.4e38f;
    for (int i = t; i < n; i += 128) m = fmaxf(m, s_p[i]);
    #pragma unroll
    for (int o = 16; o; o >>= 1) m = fmaxf(m, __shfl_xor_sync(0xffffffffu, m, o));
    if (lane == 0) s_red[w] = m;
    __syncthreads();
    m = fmaxf(fmaxf(s_red[0], s_red[1]), fmaxf(s_red[2], s_red[3]));
    __syncthreads();

    float sum = 0.f;
    for (int i = t; i < n; i += 128) {
        float e = __expf(s_p[i] - m);
        s_p[i] = e;
        sum += e;
    }
    #pragma unroll
    for (int o = 16; o; o >>= 1) sum += __shfl_xor_sync(0xffffffffu, sum, o);
    __syncthreads();
    if (lane == 0) s_red[w] = sum;
    __syncthreads();
    sum = s_red[0] + s_red[1] + s_red[2] + s_red[3];
    float inv = 1.0f / sum;

    float4 acc = make_float4(0.f, 0.f, 0.f, 0.f);
    for (int j = w; j < n; j += 4) {
        float p = s_p[j];
        int kidx = s_idx[j];
        const __half* vh = g_kvh + (size_t)kidx * (H_ * 256) + h * 256 + 128;
        uint2 raw = *reinterpret_cast<const uint2*>(vh + lane * 4);
        float2 v01 = __half22float2(*reinterpret_cast<const __half2*>(&raw.x));
        float2 v23 = __half22float2(*reinterpret_cast<const __half2*>(&raw.y));
        acc.x += p * v01.x; acc.y += p * v01.y; acc.z += p * v23.x; acc.w += p * v23.y;
    }
    reinterpret_cast<float4*>(&s_out[w][0])[lane] = acc;
    __syncthreads();
    float o = (s_out[0][t] + s_out[1][t] + s_out[2][t] + s_out[3][t]) * inv;
    g_attnh[(size_t)qi * (H_ * VDIM_) + h * VDIM_ + t] = __float2half_rn(o);
}

// ---------------- launch ----------------
extern "C" void kernel_launch(void* const* d_in, const int* in_sizes, int n_in,
                              void* d_out, int out_size) {
    (void)in_sizes; (void)n_in; (void)out_size;
    const float* hidden      = (const float*)d_in[0];
    const float* q_a_w       = (const float*)d_in[1];
    const float* q_a_ln_w    = (const float*)d_in[2];
    const float* q_b_w       = (const float*)d_in[3];
    const float* kv_a_w      = (const float*)d_in[4];
    const float* kv_a_ln_w   = (const float*)d_in[5];
    const float* kv_b_w      = (const float*)d_in[6];
    const float* o_w         = (const float*)d_in[7];
    const float* idx_wq_b_w  = (const float*)d_in[8];
    const float* idx_wk_w    = (const float*)d_in[9];
    const float* idx_kn_w    = (const float*)d_in[10];
    const float* idx_kn_b    = (const float*)d_in[11];
    const float* idx_wproj_w = (const float*)d_in[12];
    float* out = (float*)d_out;

    float  *p_qr, *p_q, *p_iq, *p_ikpre;
    __half *p_qrh, *p_attnh, *p_qbwh, *p_kvbwh, *p_owh;
    cudaGetSymbolAddress((void**)&p_qr,    g_qr);
    cudaGetSymbolAddress((void**)&p_q,     g_q);
    cudaGetSymbolAddress((void**)&p_iq,    g_iq);
    cudaGetSymbolAddress((void**)&p_ikpre, g_ikpre);
    cudaGetSymbolAddress((void**)&p_qrh,   g_qrh);
    cudaGetSymbolAddress((void**)&p_attnh, g_attnh);
    cudaGetSymbolAddress((void**)&p_qbwh,  g_qbwh);
    cudaGetSymbolAddress((void**)&p_kvbwh, g_kvbwh);
    cudaGetSymbolAddress((void**)&p_owh,   g_owh);

    dim3 tb(256);

    cossin_kernel<<<S_, 32>>>();
    build_bext_kernel<<<(CKVX_ * HID_ / 4 + 255) / 256, 256>>>(kv_a_w, idx_wproj_w);
    f2h_kernel<<<((H_*192)*QR_/4 + 255)/256, 256>>>(q_b_w,  p_qbwh,  (H_*192)*QR_/4);
    f2h_kernel<<<((H_*256)*KVR_/4 + 255)/256, 256>>>(kv_b_w, p_kvbwh, (H_*256)*KVR_/4);
    f2h_kernel<<<(HID_*(H_*VDIM_)/4 + 255)/256, 256>>>(o_w,  p_owh,   HID_*(H_*VDIM_)/4);

    // qr | ckvx(incl 0.25*iw) | ik — single wave over A=hidden (K=2048)
    fused_hidden_gemm<<<dim3(18, S_ / 128), tb>>>(hidden, q_a_w, idx_wk_w);
    rmsnorm_kernel<<<S_, 256>>>(p_qr, p_qrh, q_a_ln_w, QR_);
    ckv_split_kernel<<<S_, 256>>>(kv_a_ln_w);
    ik_ln_rope_kernel<<<S_, 128>>>(p_ikpre, idx_kn_w, idx_kn_b);

    // merged: iq (fp32, top-k critical) + q/kv tensor-core GEMMs — pipe-level overlap
    fused_mid_gemm<<<1152, tb>>>(idx_wq_b_w);

    // rope q_pe and iq
    rope_kernel<<<S_, dim3(32, H_)>>>(p_q + NOPE_, H_ * 192, 192);
    rope_kernel<<<S_, dim3(32, IH_)>>>(p_iq, IH_ * ID_, ID_);

    // fused indexer scores (causal skip + FFMA2)
    idx_scores_kernel<<<dim3(S_ / 64, S_ / 128), tb>>>();

    topk_kernel<<<S_, 256>>>();

    sparse_attn_kernel<<<dim3(S_, H_), 128>>>();

    // out = attn @ o_w^T via fp16 tensor cores
    hgemm_nt<<<dim3(HID_/128, S_/128), tb>>>(p_attnh, H_*VDIM_, p_owh, H_*VDIM_, out, HID_, H_*VDIM_, 0);
}

// round 17
// speedup vs baseline: 1.9540x; 1.3077x over previous
#include <cuda_runtime.h>
#include <cuda_fp16.h>
#include <math.h>

#define S_    2048
#define HID_  2048
#define H_    16
#define NOPE_ 128
#define ROPE_ 64
#define VDIM_ 128
#define QR_   1536
#define KVR_  512
#define IH_   16
#define ID_   128
#define TOPK_ 512
#define EPS_  1e-6f
#define CKVX_ 640

typedef unsigned long long u64;

__device__ __forceinline__ void ffma2(u64 &d, u64 a, u64 b) {
    asm("fma.rn.f32x2 %0, %1, %2, %0;" : "+l"(d) : "l"(a), "l"(b));
}
__device__ __forceinline__ u64 pack2(float lo, float hi) {
    u64 r; asm("mov.b64 %0, {%1, %2};" : "=l"(r) : "f"(lo), "f"(hi)); return r;
}
__device__ __forceinline__ float2 unpack2(u64 v) {
    float2 r; asm("mov.b64 {%0, %1}, %2;" : "=f"(r.x), "=f"(r.y) : "l"(v)); return r;
}
__device__ __forceinline__ unsigned sptr(const void* p) {
    return (unsigned)__cvta_generic_to_shared(p);
}

// ---------------- scratch ----------------
__device__ float  g_qr    [S_*QR_];
__device__ __half g_qrh   [S_*QR_];
__device__ float  g_q     [S_*H_*(NOPE_+ROPE_)];
__device__ float  g_ckvx  [S_*CKVX_];
__device__ float  g_bext  [CKVX_*HID_];
__device__ __half g_ckvnh [S_*KVR_];
__device__ __half g_kpeh  [S_*ROPE_];
__device__ __half g_kvh   [S_*H_*(NOPE_+VDIM_)];
__device__ float  g_iq    [S_*IH_*ID_];
__device__ float  g_ikpre [S_*ID_];
__device__ float  g_ik    [S_*ID_];
__device__ float  g_scores[S_*S_];
__device__ int    g_sel   [S_*TOPK_];
__device__ int    g_nsel  [S_];
__device__ __half g_attnh [S_*H_*VDIM_];
__device__ __half g_qbwh  [(H_*192)*QR_];
__device__ __half g_kvbwh [(H_*256)*KVR_];
__device__ __half g_owh   [HID_*(H_*VDIM_)];
__device__ float  g_cosb  [S_*32];
__device__ float  g_sinb  [S_*32];
// dense-attention buffers
__device__ __half g_Qf [H_*S_*192];
__device__ __half g_Kf [H_*S_*192];
__device__ __half g_Vt [H_*VDIM_*S_];
__device__ float  g_S  [H_*S_*S_];       // 268 MB
__device__ __half g_P  [H_*S_*S_];       // 134 MB
__device__ unsigned g_keep[S_*(S_/32)];

// ---------------- helpers ----------------
__device__ __forceinline__ float blockReduceSum(float v, float* sh) {
    int lane = threadIdx.x & 31, w = threadIdx.x >> 5;
    #pragma unroll
    for (int o = 16; o; o >>= 1) v += __shfl_xor_sync(0xffffffffu, v, o);
    if (lane == 0) sh[w] = v;
    __syncthreads();
    int nw = (blockDim.x + 31) >> 5;
    float r = (threadIdx.x < nw) ? sh[threadIdx.x] : 0.f;
    if (w == 0) {
        #pragma unroll
        for (int o = 16; o; o >>= 1) r += __shfl_xor_sync(0xffffffffu, r, o);
        if (lane == 0) sh[0] = r;
    }
    __syncthreads();
    float out = sh[0];
    __syncthreads();
    return out;
}
__device__ __forceinline__ float blockReduceMax(float v, float* sh) {
    int lane = threadIdx.x & 31, w = threadIdx.x >> 5;
    #pragma unroll
    for (int o = 16; o; o >>= 1) v = fmaxf(v, __shfl_xor_sync(0xffffffffu, v, o));
    if (lane == 0) sh[w] = v;
    __syncthreads();
    int nw = (blockDim.x + 31) >> 5;
    float r = (threadIdx.x < nw) ? sh[threadIdx.x] : -3.4e38f;
    if (w == 0) {
        #pragma unroll
        for (int o = 16; o; o >>= 1) r = fmaxf(r, __shfl_xor_sync(0xffffffffu, r, o));
        if (lane == 0) sh[0] = r;
    }
    __syncthreads();
    float out = sh[0];
    __syncthreads();
    return out;
}

__global__ void cossin_kernel() {
    int s = blockIdx.x, d = threadIdx.x;
    float e = (float)(2 * d) / 64.0f;
    float pf = (float)pow(10000.0, (double)e);
    float inv = __fdiv_rn(1.0f, pf);
    float f = __fmul_rn((float)s, inv);
    g_cosb[s * 32 + d] = (float)cos((double)f);
    g_sinb[s * 32 + d] = (float)sin((double)f);
}

__global__ __launch_bounds__(256) void f2h_kernel(const float* __restrict__ src,
                                                  __half* __restrict__ dst, int n4) {
    int i = blockIdx.x * 256 + threadIdx.x;
    if (i < n4) {
        float4 v = reinterpret_cast<const float4*>(src)[i];
        reinterpret_cast<__half2*>(dst)[i * 2]     = __floats2half2_rn(v.x, v.y);
        reinterpret_cast<__half2*>(dst)[i * 2 + 1] = __floats2half2_rn(v.z, v.w);
    }
}

__global__ __launch_bounds__(256) void build_bext_kernel(
    const float* __restrict__ kv_a_w, const float* __restrict__ idx_wproj_w)
{
    size_t idx = (size_t)blockIdx.x * 256 + threadIdx.x;
    size_t row = idx / (HID_ / 4), c4 = idx % (HID_ / 4);
    float4 v;
    if (row < 576) {
        v = reinterpret_cast<const float4*>(kv_a_w)[row * (HID_ / 4) + c4];
    } else if (row < 592) {
        v = reinterpret_cast<const float4*>(idx_wproj_w)[(row - 576) * (HID_ / 4) + c4];
        v.x *= 0.25f; v.y *= 0.25f; v.z *= 0.25f; v.w *= 0.25f;
    } else {
        v = make_float4(0.f, 0.f, 0.f, 0.f);
    }
    reinterpret_cast<float4*>(g_bext)[idx] = v;
}

// ============ fp32 GEMM body (indexer-critical path) ============
__device__ __forceinline__ void gemm_body_128(
    const float* __restrict__ A, int lda,
    const float* __restrict__ B, int ldb,
    float* __restrict__ C, int ldc,
    int M, int N, int K, float alpha,
    int m0, int n0,
    float (*As)[8][128], float (*Bs)[8][128])
{
    int t = threadIdx.x;
    int tx = t & 15, ty = t >> 4;
    int a_m = t >> 1, a_k = (t & 1) * 4;
    int gmA = m0 + a_m, gnB = n0 + a_m;
    u64 acc[8][4];
    #pragma unroll
    for (int i = 0; i < 8; i++)
        #pragma unroll
        for (int j = 0; j < 4; j++) acc[i][j] = 0ull;

    float4 va = make_float4(0.f,0.f,0.f,0.f), vb = va;
    if (gmA < M) va = *reinterpret_cast<const float4*>(&A[(size_t)gmA * lda + a_k]);
    if (gnB < N) vb = *reinterpret_cast<const float4*>(&B[(size_t)gnB * ldb + a_k]);
    As[0][a_k+0][a_m]=va.x; As[0][a_k+1][a_m]=va.y; As[0][a_k+2][a_m]=va.z; As[0][a_k+3][a_m]=va.w;
    Bs[0][a_k+0][a_m]=vb.x; Bs[0][a_k+1][a_m]=vb.y; Bs[0][a_k+2][a_m]=vb.z; Bs[0][a_k+3][a_m]=vb.w;
    __syncthreads();
    int buf = 0;
    for (int k0 = 0; k0 < K; k0 += 8) {
        bool nxt = (k0 + 8) < K;
        if (nxt) {
            va = make_float4(0.f,0.f,0.f,0.f); vb = va;
            if (gmA < M) va = *reinterpret_cast<const float4*>(&A[(size_t)gmA * lda + k0 + 8 + a_k]);
            if (gnB < N) vb = *reinterpret_cast<const float4*>(&B[(size_t)gnB * ldb + k0 + 8 + a_k]);
        }
        #pragma unroll
        for (int k = 0; k < 8; k++) {
            float4 a0 = *reinterpret_cast<const float4*>(&As[buf][k][ty * 4]);
            float4 a1 = *reinterpret_cast<const float4*>(&As[buf][k][64 + ty * 4]);
            float4 b0 = *reinterpret_cast<const float4*>(&Bs[buf][k][tx * 4]);
            float4 b1 = *reinterpret_cast<const float4*>(&Bs[buf][k][64 + tx * 4]);
            u64 bb[4] = {pack2(b0.x,b0.y), pack2(b0.z,b0.w), pack2(b1.x,b1.y), pack2(b1.z,b1.w)};
            float ra[8] = {a0.x,a0.y,a0.z,a0.w,a1.x,a1.y,a1.z,a1.w};
            #pragma unroll
            for (int i = 0; i < 8; i++) {
                u64 aa = pack2(ra[i], ra[i]);
                #pragma unroll
                for (int j = 0; j < 4; j++) ffma2(acc[i][j], aa, bb[j]);
            }
        }
        if (nxt) {
            int nb = buf ^ 1;
            As[nb][a_k+0][a_m]=va.x; As[nb][a_k+1][a_m]=va.y; As[nb][a_k+2][a_m]=va.z; As[nb][a_k+3][a_m]=va.w;
            Bs[nb][a_k+0][a_m]=vb.x; Bs[nb][a_k+1][a_m]=vb.y; Bs[nb][a_k+2][a_m]=vb.z; Bs[nb][a_k+3][a_m]=vb.w;
            __syncthreads();
            buf = nb;
        }
    }
    #pragma unroll
    for (int i = 0; i < 8; i++) {
        int gm = m0 + ((i < 4) ? (ty * 4 + i) : (64 + ty * 4 + i - 4));
        if (gm >= M) continue;
        #pragma unroll
        for (int j = 0; j < 4; j++) {
            float2 v = unpack2(acc[i][j]);
            int gn = n0 + ((j < 2) ? (tx * 4 + j * 2) : (64 + tx * 4 + (j - 2) * 2));
            if (gn < N)     C[(size_t)gm * ldc + gn]     = alpha * v.x;
            if (gn + 1 < N) C[(size_t)gm * ldc + gn + 1] = alpha * v.y;
        }
    }
}

// ---------------- fused A=hidden (K=2048): qr | ckvx(incl iw) | ik ----------------
__global__ __launch_bounds__(256, 2) void fused_hidden_gemm(
    const float* __restrict__ A,
    const float* __restrict__ Bqr, const float* __restrict__ Bik)
{
    __shared__ float As[2][8][128];
    __shared__ float Bs[2][8][128];
    int bx = blockIdx.x;
    const float* B; float* C; int N, ldc, n0;
    if (bx < 12)      { B = Bqr;    C = g_qr;    N = QR_;   ldc = QR_;   n0 = bx * 128; }
    else if (bx < 17) { B = g_bext; C = g_ckvx;  N = CKVX_; ldc = CKVX_; n0 = (bx - 12) * 128; }
    else              { B = Bik;    C = g_ikpre; N = ID_;   ldc = ID_;   n0 = 0; }
    gemm_body_128(A, HID_, B, HID_, C, ldc, S_, N, HID_, 1.f,
                  blockIdx.y * 128, n0, As, Bs);
}

// ============ fp16 tensor-core GEMM body (fp32 accumulate) ============
#define AS_H(b,r,c) Ash[(b)*3072 + (r)*24 + (c)]
#define BS_H(b,r,c) Bsh[(b)*3072 + (r)*24 + (c)]
__device__ __forceinline__ void hgemm_body(
    const __half* __restrict__ A, int lda,
    const __half* __restrict__ B, int ldb,
    void* __restrict__ Cv, int ldc,
    int K, int halfOut, int m0, int n0,
    __half* Ash, __half* Bsh)
{
    int t = threadIdx.x;
    int lane = t & 31, wid = t >> 5;
    int wm = (wid & 1) * 64, wn = (wid >> 1) * 32;
    int l_r = t >> 1, l_c = (t & 1) * 8;

    float acc[4][4][4];
    #pragma unroll
    for (int i = 0; i < 4; i++)
        #pragma unroll
        for (int j = 0; j < 4; j++)
            #pragma unroll
            for (int c = 0; c < 4; c++) acc[i][j][c] = 0.f;

    uint4 va = *reinterpret_cast<const uint4*>(&A[(size_t)(m0 + l_r) * lda + l_c]);
    uint4 vb = *reinterpret_cast<const uint4*>(&B[(size_t)(n0 + l_r) * ldb + l_c]);
    *reinterpret_cast<uint4*>(&AS_H(0, l_r, l_c)) = va;
    *reinterpret_cast<uint4*>(&BS_H(0, l_r, l_c)) = vb;
    __syncthreads();

    int a_row = lane & 15, a_col = (lane >> 4) * 8;
    int b_row = lane & 7,  b_col = ((lane >> 3) & 1) * 8;

    int buf = 0;
    for (int k0 = 0; k0 < K; k0 += 16) {
        bool nxt = (k0 + 16) < K;
        if (nxt) {
            va = *reinterpret_cast<const uint4*>(&A[(size_t)(m0 + l_r) * lda + k0 + 16 + l_c]);
            vb = *reinterpret_cast<const uint4*>(&B[(size_t)(n0 + l_r) * ldb + k0 + 16 + l_c]);
        }
        unsigned af[4][4], bf[4][2];
        #pragma unroll
        for (int i = 0; i < 4; i++) {
            unsigned addr = sptr(&AS_H(buf, wm + 16 * i + a_row, a_col));
            asm volatile("ldmatrix.sync.aligned.m8n8.x4.shared.b16 {%0,%1,%2,%3}, [%4];"
                : "=r"(af[i][0]), "=r"(af[i][1]), "=r"(af[i][2]), "=r"(af[i][3]) : "r"(addr));
        }
        #pragma unroll
        for (int j = 0; j < 4; j++) {
            unsigned addr = sptr(&BS_H(buf, wn + 8 * j + b_row, b_col));
            asm volatile("ldmatrix.sync.aligned.m8n8.x2.shared.b16 {%0,%1}, [%2];"
                : "=r"(bf[j][0]), "=r"(bf[j][1]) : "r"(addr));
        }
        #pragma unroll
        for (int i = 0; i < 4; i++)
            #pragma unroll
            for (int j = 0; j < 4; j++)
                asm volatile("mma.sync.aligned.m16n8k16.row.col.f32.f16.f16.f32 "
                    "{%0,%1,%2,%3}, {%4,%5,%6,%7}, {%8,%9}, {%0,%1,%2,%3};"
                    : "+f"(acc[i][j][0]), "+f"(acc[i][j][1]), "+f"(acc[i][j][2]), "+f"(acc[i][j][3])
                    : "r"(af[i][0]), "r"(af[i][1]), "r"(af[i][2]), "r"(af[i][3]),
                      "r"(bf[j][0]), "r"(bf[j][1]));
        if (nxt) {
            int nb = buf ^ 1;
            *reinterpret_cast<uint4*>(&AS_H(nb, l_r, l_c)) = va;
            *reinterpret_cast<uint4*>(&BS_H(nb, l_r, l_c)) = vb;
            __syncthreads();
            buf = nb;
        }
    }

    int r = lane >> 2, cpair = (lane & 3) * 2;
    #pragma unroll
    for (int i = 0; i < 4; i++) {
        int gm0 = m0 + wm + 16 * i + r;
        #pragma unroll
        for (int j = 0; j < 4; j++) {
            int gn = n0 + wn + 8 * j + cpair;
            if (halfOut) {
                __half* C = reinterpret_cast<__half*>(Cv);
                *reinterpret_cast<__half2*>(&C[(size_t)gm0 * ldc + gn]) =
                    __floats2half2_rn(acc[i][j][0], acc[i][j][1]);
                *reinterpret_cast<__half2*>(&C[(size_t)(gm0 + 8) * ldc + gn]) =
                    __floats2half2_rn(acc[i][j][2], acc[i][j][3]);
            } else {
                float* C = reinterpret_cast<float*>(Cv);
                C[(size_t)gm0 * ldc + gn]           = acc[i][j][0];
                C[(size_t)gm0 * ldc + gn + 1]       = acc[i][j][1];
                C[(size_t)(gm0 + 8) * ldc + gn]     = acc[i][j][2];
                C[(size_t)(gm0 + 8) * ldc + gn + 1] = acc[i][j][3];
            }
        }
    }
}

// ---------------- standalone hgemm (o_w) ----------------
__global__ __launch_bounds__(256, 2) void hgemm_nt(
    const __half* __restrict__ A, int lda,
    const __half* __restrict__ B, int ldb,
    void* __restrict__ Cv, int ldc,
    int K, int halfOut)
{
    __shared__ __half smemh[2 * 3072 * 2];
    hgemm_body(A, lda, B, ldb, Cv, ldc, K, halfOut,
               blockIdx.y * 128, blockIdx.x * 128, smemh, smemh + 2 * 3072);
}

// ---------------- S = Q@K^T per head (causal tile skip) ----------------
__global__ __launch_bounds__(256, 2) void hgemm_s_kernel() {
    int n0 = blockIdx.x * 128, m0 = blockIdx.y * 128, h = blockIdx.z;
    if (n0 > m0 + 127) return;
    __shared__ __half smemh[2 * 3072 * 2];
    hgemm_body(g_Qf + (size_t)h * S_ * 192, 192,
               g_Kf + (size_t)h * S_ * 192, 192,
               g_S + (size_t)h * S_ * S_, S_,
               192, 0, m0, n0, smemh, smemh + 2 * 3072);
}

// ---------------- O = P@V per head (k-limit by causal structure) ----------------
__global__ __launch_bounds__(256, 2) void hgemm_pv_kernel() {
    int m0 = blockIdx.x * 128, h = blockIdx.y;
    __shared__ __half smemh[2 * 3072 * 2];
    hgemm_body(g_P + (size_t)h * S_ * S_, S_,
               g_Vt + (size_t)h * VDIM_ * S_, S_,
               g_attnh + h * VDIM_, H_ * VDIM_,
               m0 + 128, 1, m0, 0, smemh, smemh + 2 * 3072);
}

// ============ merged mid-stage: iq (fp32) | q hgemm | kv hgemm ============
__global__ __launch_bounds__(256, 2) void fused_mid_gemm(
    const float* __restrict__ Biq)
{
    __shared__ char smem[24576];
    int bx = blockIdx.x;
    if (bx < 256) {
        float (*As)[8][128] = reinterpret_cast<float (*)[8][128]>(smem);
        float (*Bs)[8][128] = reinterpret_cast<float (*)[8][128]>(smem + 8192);
        int n0 = (bx & 15) * 128, m0 = (bx >> 4) * 128;
        gemm_body_128(g_qr, QR_, Biq, QR_, g_iq, IH_ * ID_, S_, IH_ * ID_, QR_, 1.f,
                      m0, n0, As, Bs);
    } else if (bx < 640) {
        __half* Ash = reinterpret_cast<__half*>(smem);
        __half* Bsh = Ash + 2 * 3072;
        int idx = bx - 256;
        int n0 = (idx % 24) * 128, m0 = (idx / 24) * 128;
        hgemm_body(g_qrh, QR_, g_qbwh, QR_, g_q, H_ * 192, QR_, 0, m0, n0, Ash, Bsh);
    } else {
        __half* Ash = reinterpret_cast<__half*>(smem);
        __half* Bsh = Ash + 2 * 3072;
        int idx = bx - 640;
        int n0 = (idx & 31) * 128, m0 = (idx >> 5) * 128;
        hgemm_body(g_ckvnh, KVR_, g_kvbwh, KVR_, g_kvh, H_ * 256, KVR_, 1, m0, n0, Ash, Bsh);
    }
}

// ---------------- rmsnorm (in-place fp32 + fp16 copy) ----------------
__global__ __launch_bounds__(256) void rmsnorm_kernel(float* __restrict__ x,
                                                      __half* __restrict__ xh,
                                                      const float* __restrict__ w, int n) {
    __shared__ float sh[33];
    int row = blockIdx.x, t = threadIdx.x;
    float* p = x + (size_t)row * n;
    int cnt = n / 256;
    float local[8];
    float ss = 0.f;
    for (int i = 0; i < cnt; i++) { float v = p[t + i * 256]; local[i] = v; ss += v * v; }
    float total = blockReduceSum(ss, sh);
    float scale = rsqrtf(total / (float)n + EPS_);
    for (int i = 0; i < cnt; i++) {
        float o = local[i] * scale * w[t + i * 256];
        p[t + i * 256] = o;
        xh[(size_t)row * n + t + i * 256] = __float2half_rn(o);
    }
}

// ---------------- ckv split (ckvn fp16; kpe fp16) ----------------
__global__ __launch_bounds__(256) void ckv_split_kernel(const float* __restrict__ w) {
    __shared__ float sh[33];
    int s = blockIdx.x, t = threadIdx.x;
    const float* p = g_ckvx + (size_t)s * CKVX_;
    float v0 = p[t], v1 = p[256 + t];
    float total = blockReduceSum(v0 * v0 + v1 * v1, sh);
    float scale = rsqrtf(total / (float)KVR_ + EPS_);
    g_ckvnh[(size_t)s * KVR_ + t]       = __float2half_rn(v0 * scale * w[t]);
    g_ckvnh[(size_t)s * KVR_ + 256 + t] = __float2half_rn(v1 * scale * w[256 + t]);
    if (t < 32) {
        float x1 = p[KVR_ + t], x2 = p[KVR_ + 32 + t];
        float c = g_cosb[s * 32 + t], sn = g_sinb[s * 32 + t];
        g_kpeh[s * ROPE_ + t]      = __float2half_rn(x1 * c - x2 * sn);
        g_kpeh[s * ROPE_ + 32 + t] = __float2half_rn(x2 * c + x1 * sn);
    }
}

// ---------------- layernorm + rope for ik ----------------
__global__ __launch_bounds__(128) void ik_ln_rope_kernel(const float* __restrict__ xin,
                                                         const float* __restrict__ w,
                                                         const float* __restrict__ b) {
    __shared__ float sh[33];
    __shared__ float sn_[128];
    int s = blockIdx.x, t = threadIdx.x;
    float x = xin[(size_t)s * ID_ + t];
    float mean = blockReduceSum(x, sh) / (float)ID_;
    float var = blockReduceSum(x * x, sh) / (float)ID_ - mean * mean;
    float nv = (x - mean) * rsqrtf(var + EPS_) * w[t] + b[t];
    sn_[t] = nv;
    __syncthreads();
    float out;
    if (t < 32) {
        float c = g_cosb[s * 32 + t], snv = g_sinb[s * 32 + t];
        out = sn_[t] * c - sn_[t + 32] * snv;
    } else if (t < 64) {
        float c = g_cosb[s * 32 + (t - 32)], snv = g_sinb[s * 32 + (t - 32)];
        out = sn_[t] * c + sn_[t - 32] * snv;
    } else {
        out = nv;
    }
    g_ik[(size_t)s * ID_ + t] = out;
}

// ---------------- generic in-place rope over heads ----------------
__global__ void rope_kernel(float* __restrict__ base, int rowStride, int headStride) {
    int s = blockIdx.x;
    int h = threadIdx.y, d = threadIdx.x;
    float* p = base + (size_t)s * rowStride + h * headStride;
    float c = g_cosb[s * 32 + d], sn = g_sinb[s * 32 + d];
    float x1 = p[d], x2 = p[d + 32];
    p[d] = x1 * c - x2 * sn;
    p[d + 32] = x2 * c + x1 * sn;
}

// ---------------- pack Qf (post-rope) and Kf = kn|kpe, per-head fp16 ----------------
__global__ __launch_bounds__(256) void pack_qk_kernel() {
    int s = blockIdx.x, t = threadIdx.x;
    for (int idx = t; idx < H_ * 192; idx += 256) {
        int h = idx / 192, d = idx % 192;
        g_Qf[((size_t)h * S_ + s) * 192 + d] =
            __float2half_rn(g_q[(size_t)s * (H_ * 192) + idx]);
        __half kv;
        if (d < 128) kv = g_kvh[(size_t)s * (H_ * 256) + h * 256 + d];
        else         kv = g_kpeh[s * ROPE_ + (d - 128)];
        g_Kf[((size_t)h * S_ + s) * 192 + d] = kv;
    }
}

// ---------------- Vt transpose (smem tiled) ----------------
__global__ __launch_bounds__(256) void vt_transpose_kernel() {
    __shared__ __half sm[128][130];
    int s0 = blockIdx.x * 128, h = blockIdx.y;
    int t = threadIdx.x;
    for (int idx = t; idx < 128 * 128; idx += 256) {
        int s = idx >> 7, d = idx & 127;
        sm[d][s] = g_kvh[(size_t)(s0 + s) * (H_ * 256) + h * 256 + 128 + d];
    }
    __syncthreads();
    for (int idx = t; idx < 128 * 128; idx += 256) {
        int d = idx >> 7, s = idx & 127;
        g_Vt[((size_t)h * VDIM_ + d) * S_ + s0 + s] = sm[d][s];
    }
}

// ============ fused indexer w/ FFMA2 + causal skip ============
__global__ __launch_bounds__(256, 2) void idx_scores_kernel() {
    int m0 = blockIdx.y * 128, n0 = blockIdx.x * 64;
    int t = threadIdx.x;
    int tx = t & 15, ty = t >> 4;
    const float NINF = __int_as_float(0xff800000);

    if (m0 + 128 <= TOPK_) return;
    if (n0 >= m0 + 128) {
        #pragma unroll
        for (int i = 0; i < 8; i++) {
            int gm = m0 + ty * 8 + i;
            #pragma unroll
            for (int j = 0; j < 4; j++)
                g_scores[(size_t)gm * S_ + n0 + tx * 4 + j] = NINF;
        }
        return;
    }

    __shared__ float Bs[128][64];
    __shared__ float As[2][8][128];
    int a_m = t >> 1, a_k = (t & 1) * 4;

    for (int i = t; i < 64 * 32; i += 256) {
        int nl = i >> 5, k4 = (i & 31) * 4;
        float4 v = *reinterpret_cast<const float4*>(&g_ik[(size_t)(n0 + nl) * ID_ + k4]);
        Bs[k4+0][nl] = v.x; Bs[k4+1][nl] = v.y; Bs[k4+2][nl] = v.z; Bs[k4+3][nl] = v.w;
    }

    float sacc[8][4];
    #pragma unroll
    for (int i = 0; i < 8; i++)
        #pragma unroll
        for (int j = 0; j < 4; j++) sacc[i][j] = 0.f;
    __syncthreads();

    const size_t lda = IH_ * ID_;
    for (int h = 0; h < IH_; h++) {
        const float* A = g_iq + (size_t)h * ID_ + (size_t)(m0 + a_m) * lda;
        {
            float4 v = *reinterpret_cast<const float4*>(&A[a_k]);
            As[0][a_k+0][a_m]=v.x; As[0][a_k+1][a_m]=v.y; As[0][a_k+2][a_m]=v.z; As[0][a_k+3][a_m]=v.w;
        }
        __syncthreads();
        u64 tacc[8][2];
        #pragma unroll
        for (int i = 0; i < 8; i++) { tacc[i][0] = 0ull; tacc[i][1] = 0ull; }
        int buf = 0;
        for (int k0 = 0; k0 < 128; k0 += 8) {
            float4 v;
            bool nxt = (k0 + 8) < 128;
            if (nxt) v = *reinterpret_cast<const float4*>(&A[k0 + 8 + a_k]);
            #pragma unroll
            for (int k = 0; k < 8; k++) {
                float4 a0 = *reinterpret_cast<const float4*>(&As[buf][k][ty * 8]);
                float4 a1 = *reinterpret_cast<const float4*>(&As[buf][k][ty * 8 + 4]);
                float4 b0 = *reinterpret_cast<const float4*>(&Bs[k0 + k][tx * 4]);
                u64 bb[2] = {pack2(b0.x,b0.y), pack2(b0.z,b0.w)};
                float ra[8] = {a0.x,a0.y,a0.z,a0.w,a1.x,a1.y,a1.z,a1.w};
                #pragma unroll
                for (int i = 0; i < 8; i++) {
                    u64 aa = pack2(ra[i], ra[i]);
                    ffma2(tacc[i][0], aa, bb[0]);
                    ffma2(tacc[i][1], aa, bb[1]);
                }
            }
            if (nxt) {
                int nb = buf ^ 1;
                As[nb][a_k+0][a_m]=v.x; As[nb][a_k+1][a_m]=v.y; As[nb][a_k+2][a_m]=v.z; As[nb][a_k+3][a_m]=v.w;
                __syncthreads();
                buf = nb;
            }
        }
        __syncthreads();
        #pragma unroll
        for (int i = 0; i < 8; i++) {
            float w = g_ckvx[(size_t)(m0 + ty * 8 + i) * CKVX_ + 576 + h];
            float2 t01 = unpack2(tacc[i][0]);
            float2 t23 = unpack2(tacc[i][1]);
            float tv[4] = {t01.x, t01.y, t23.x, t23.y};
            #pragma unroll
            for (int j = 0; j < 4; j++) {
                float add = __fmul_rn(w, fmaxf(tv[j], 0.f));
                sacc[i][j] = __fadd_rn(sacc[i][j], add);
            }
        }
    }
    #pragma unroll
    for (int i = 0; i < 8; i++) {
        int gm = m0 + ty * 8 + i;
        #pragma unroll
        for (int j = 0; j < 4; j++) {
            int gn = n0 + tx * 4 + j;
            g_scores[(size_t)gm * S_ + gn] = (gn <= gm) ? sacc[i][j] : NINF;
        }
    }
}

// ---------------- top-k (stable, jax tie semantics) ----------------
__device__ __forceinline__ unsigned fkey(float f) {
    unsigned u = __float_as_uint(f);
    return u ^ ((u >> 31) ? 0xFFFFFFFFu : 0x80000000u);
}

__global__ __launch_bounds__(256) void topk_kernel() {
    int q = blockIdx.x, t = threadIdx.x;
    const float* sc = g_scores + (size_t)q * S_;
    if (q < TOPK_) {
        for (int i = t; i <= q; i += 256) g_sel[(size_t)q * TOPK_ + i] = i;
        if (t == 0) g_nsel[q] = q + 1;
        return;
    }
    __shared__ unsigned hist[256];
    __shared__ unsigned s_pref, s_r;
    __shared__ int s_gt[257], s_eq[257];

    unsigned pref = 0, r = TOPK_;
    #pragma unroll
    for (int p = 3; p >= 0; p--) {
        hist[t] = 0;
        __syncthreads();
        for (int i = t; i < S_; i += 256) {
            unsigned u = fkey(sc[i]);
            bool ok = (p == 3) || ((u >> ((p + 1) * 8)) == pref);
            if (ok) atomicAdd(&hist[(u >> (p * 8)) & 255], 1u);
        }
        __syncthreads();
        if (t == 0) {
            unsigned run = 0;
            int b = 255;
            for (; b >= 0; b--) {
                unsigned c = hist[b];
                if (run + c >= r) break;
                run += c;
            }
            s_pref = (pref << 8) | (unsigned)b;
            s_r = r - run;
        }
        __syncthreads();
        pref = s_pref; r = s_r;
        __syncthreads();
    }
    unsigned T = pref;
    int need_eq = (int)r;

    int i0 = t * 8;
    unsigned keys[8];
    int cg = 0, ce = 0;
    #pragma unroll
    for (int k = 0; k < 8; k++) {
        unsigned u = fkey(sc[i0 + k]);
        keys[k] = u;
        cg += (u > T);
        ce += (u == T);
    }
    s_gt[t] = cg; s_eq[t] = ce;
    __syncthreads();
    if (t == 0) {
        int rg = 0, re = 0;
        for (int i = 0; i < 256; i++) {
            int a = s_gt[i]; s_gt[i] = rg; rg += a;
            int b2 = s_eq[i]; s_eq[i] = re; re += b2;
        }
        s_gt[256] = rg;
    }
    __syncthreads();
    int gpos = s_gt[t], epos = s_eq[t], total_gt = s_gt[256];
    int* out = g_sel + (size_t)q * TOPK_;
    #pragma unroll
    for (int k = 0; k < 8; k++) {
        unsigned u = keys[k];
        if (u > T) out[gpos++] = i0 + k;
        else if (u == T) {
            if (epos < need_eq) out[total_gt + epos] = i0 + k;
            epos++;
        }
    }
    if (t == 0) g_nsel[q] = TOPK_;
}

// ---------------- keep-mask build ----------------
__global__ __launch_bounds__(256) void keep_clear_kernel() {
    int i = blockIdx.x * 256 + threadIdx.x;
    g_keep[i] = 0u;
}
__global__ __launch_bounds__(256) void keep_scatter_kernel() {
    int q = blockIdx.x, t = threadIdx.x;
    int n = g_nsel[q];
    for (int j = t; j < n; j += 256) {
        int k = g_sel[(size_t)q * TOPK_ + j];
        atomicOr(&g_keep[q * (S_ / 32) + (k >> 5)], 1u << (k & 31));
    }
}

// ---------------- masked softmax: S (fp32) -> P (fp16) ----------------
__global__ __launch_bounds__(256) void masked_softmax_kernel() {
    __shared__ float sh[33];
    int q = blockIdx.x, h = blockIdx.y, t = threadIdx.x;
    const float SCALE = 0.07216878364870322f;
    const float* srow = g_S + ((size_t)h * S_ + q) * S_;
    __half* prow = g_P + ((size_t)h * S_ + q) * S_;
    const unsigned* mrow = g_keep + q * (S_ / 32);
    int qlim = ((q >> 7) + 1) << 7;      // PV reads P[q, 0..qlim); rest never read

    float vals[8]; bool ok[8];
    float m = -3.4e38f;
    #pragma unroll
    for (int i = 0; i < 8; i++) {
        int c = t + i * 256;
        bool a = (c < qlim) && ((mrow[c >> 5] >> (c & 31)) & 1u);
        ok[i] = a;
        float v = a ? srow[c] * SCALE : -3.4e38f;
        vals[i] = v;
        m = fmaxf(m, v);
    }
    m = blockReduceMax(m, sh);
    float sum = 0.f;
    #pragma unroll
    for (int i = 0; i < 8; i++) {
        float e = ok[i] ? __expf(vals[i] - m) : 0.f;
        vals[i] = e;
        sum += e;
    }
    sum = blockReduceSum(sum, sh);
    float inv = 1.0f / sum;
    #pragma unroll
    for (int i = 0; i < 8; i++) {
        int c = t + i * 256;
        if (c < qlim) prow[c] = __float2half_rn(vals[i] * inv);
    }
}

// ---------------- launch ----------------
extern "C" void kernel_launch(void* const* d_in, const int* in_sizes, int n_in,
                              void* d_out, int out_size) {
    (void)in_sizes; (void)n_in; (void)out_size;
    const float* hidden      = (const float*)d_in[0];
    const float* q_a_w       = (const float*)d_in[1];
    const float* q_a_ln_w    = (const float*)d_in[2];
    const float* q_b_w       = (const float*)d_in[3];
    const float* kv_a_w      = (const float*)d_in[4];
    const float* kv_a_ln_w   = (const float*)d_in[5];
    const float* kv_b_w      = (const float*)d_in[6];
    const float* o_w         = (const float*)d_in[7];
    const float* idx_wq_b_w  = (const float*)d_in[8];
    const float* idx_wk_w    = (const float*)d_in[9];
    const float* idx_kn_w    = (const float*)d_in[10];
    const float* idx_kn_b    = (const float*)d_in[11];
    const float* idx_wproj_w = (const float*)d_in[12];
    float* out = (float*)d_out;

    float  *p_qr, *p_q, *p_iq, *p_ikpre;
    __half *p_qrh, *p_attnh, *p_qbwh, *p_kvbwh, *p_owh;
    cudaGetSymbolAddress((void**)&p_qr,    g_qr);
    cudaGetSymbolAddress((void**)&p_q,     g_q);
    cudaGetSymbolAddress((void**)&p_iq,    g_iq);
    cudaGetSymbolAddress((void**)&p_ikpre, g_ikpre);
    cudaGetSymbolAddress((void**)&p_qrh,   g_qrh);
    cudaGetSymbolAddress((void**)&p_attnh, g_attnh);
    cudaGetSymbolAddress((void**)&p_qbwh,  g_qbwh);
    cudaGetSymbolAddress((void**)&p_kvbwh, g_kvbwh);
    cudaGetSymbolAddress((void**)&p_owh,   g_owh);

    dim3 tb(256);

    cossin_kernel<<<S_, 32>>>();
    build_bext_kernel<<<(CKVX_ * HID_ / 4 + 255) / 256, 256>>>(kv_a_w, idx_wproj_w);
    f2h_kernel<<<((H_*192)*QR_/4 + 255)/256, 256>>>(q_b_w,  p_qbwh,  (H_*192)*QR_/4);
    f2h_kernel<<<((H_*256)*KVR_/4 + 255)/256, 256>>>(kv_b_w, p_kvbwh, (H_*256)*KVR_/4);
    f2h_kernel<<<(HID_*(H_*VDIM_)/4 + 255)/256, 256>>>(o_w,  p_owh,   HID_*(H_*VDIM_)/4);

    // qr | ckvx(incl 0.25*iw) | ik — single wave over A=hidden (K=2048)
    fused_hidden_gemm<<<dim3(18, S_ / 128), tb>>>(hidden, q_a_w, idx_wk_w);
    rmsnorm_kernel<<<S_, 256>>>(p_qr, p_qrh, q_a_ln_w, QR_);
    ckv_split_kernel<<<S_, 256>>>(kv_a_ln_w);
    ik_ln_rope_kernel<<<S_, 128>>>(p_ikpre, idx_kn_w, idx_kn_b);

    // merged: iq (fp32, top-k critical) + q/kv tensor-core GEMMs
    fused_mid_gemm<<<1152, tb>>>(idx_wq_b_w);

    // rope q_pe and iq
    rope_kernel<<<S_, dim3(32, H_)>>>(p_q + NOPE_, H_ * 192, 192);
    rope_kernel<<<S_, dim3(32, IH_)>>>(p_iq, IH_ * ID_, ID_);

    // pack per-head Q/K (fp16) and transposed V; dense S = Q@K^T (causal skip)
    pack_qk_kernel<<<S_, 256>>>();
    vt_transpose_kernel<<<dim3(S_ / 128, H_), 256>>>();
    hgemm_s_kernel<<<dim3(16, 16, H_), tb>>>();

    // indexer scores + top-k + keep mask
    idx_scores_kernel<<<dim3(S_ / 64, S_ / 128), tb>>>();
    topk_kernel<<<S_, 256>>>();
    keep_clear_kernel<<<(S_ * (S_ / 32)) / 256, 256>>>();
    keep_scatter_kernel<<<S_, 256>>>();

    // masked softmax S->P, then O = P@V (k-limited)
    masked_softmax_kernel<<<dim3(S_, H_), 256>>>();
    hgemm_pv_kernel<<<dim3(16, H_), tb>>>();

    // out = attn @ o_w^T via fp16 tensor cores
    hgemm_nt<<<dim3(HID_/128, S_/128), tb>>>(p_attnh, H_*VDIM_, p_owh, H_*VDIM_, out, HID_, H_*VDIM_, 0);
}